// round 15
// baseline (speedup 1.0000x reference)
#include <cuda_runtime.h>
#include <cuda_fp16.h>
#include <math.h>
#include <cstdint>

#define E_DIM 1024
#define H_NUM 16
#define D_DIM 64
#define B_NUM 4
#define S_LEN 1024
#define F_DIM 4096
#define M_ROWS (B_NUM * S_LEN)  // 4096
#define MB1 (1024 * 1024)

// ---------------- scratch (static device globals) ---------------------------
// Weight slots (single fp16, [N][K] transposed): QKV1 0-2, QKV2 3-5, Wo1 6, Wo2 7,
// Wup 8-11, Wdn 12-15.
__device__ __align__(16) half g_W16[16 * MB1];
__device__ __align__(16) half g_h16[4 * MB1];          // LN out
__device__ __align__(16) half g_e16[4 * MB1];          // enc
__device__ __align__(16) half g_q16[4 * MB1];          // Q
__device__ __align__(16) half g_k16[4 * MB1];          // K1
__device__ __align__(16) half g_v16[4 * MB1];          // V1
__device__ __align__(16) half g_k2[4 * MB1];           // K2
__device__ __align__(16) half g_v2[4 * MB1];           // V2
__device__ __align__(16) half g_a16[16 * MB1];         // attn out / GELU out
__device__ __align__(16) float g_x1[4 * MB1], g_x2[4 * MB1];

// ---------------- PTX helpers -----------------------------------------------
__device__ __forceinline__ uint32_t smem_u32(const void* p) {
    uint32_t a;
    asm("{ .reg .u64 t; cvta.to.shared.u64 t, %1; cvt.u32.u64 %0, t; }" : "=r"(a) : "l"(p));
    return a;
}
__device__ __forceinline__ void cpasync16(uint32_t dst, const void* src) {
    asm volatile("cp.async.cg.shared.global [%0], [%1], 16;" :: "r"(dst), "l"(src));
}
__device__ __forceinline__ void cpcommit() { asm volatile("cp.async.commit_group;" ::: "memory"); }
template <int N>
__device__ __forceinline__ void cpwait() { asm volatile("cp.async.wait_group %0;" :: "n"(N) : "memory"); }

__device__ __forceinline__ void ldsm4(uint32_t (&r)[4], uint32_t addr) {
    asm volatile("ldmatrix.sync.aligned.m8n8.x4.shared.b16 {%0,%1,%2,%3}, [%4];"
                 : "=r"(r[0]), "=r"(r[1]), "=r"(r[2]), "=r"(r[3]) : "r"(addr));
}
__device__ __forceinline__ void ldsm4t(uint32_t (&r)[4], uint32_t addr) {
    asm volatile("ldmatrix.sync.aligned.m8n8.x4.trans.shared.b16 {%0,%1,%2,%3}, [%4];"
                 : "=r"(r[0]), "=r"(r[1]), "=r"(r[2]), "=r"(r[3]) : "r"(addr));
}
__device__ __forceinline__ void mma16816h(float (&d)[4], const uint32_t (&a)[4],
                                          const uint32_t (&b)[2]) {
    asm volatile(
        "mma.sync.aligned.m16n8k16.row.col.f32.f16.f16.f32 "
        "{%0,%1,%2,%3}, {%4,%5,%6,%7}, {%8,%9}, {%0,%1,%2,%3};"
        : "+f"(d[0]), "+f"(d[1]), "+f"(d[2]), "+f"(d[3])
        : "r"(a[0]), "r"(a[1]), "r"(a[2]), "r"(a[3]), "r"(b[0]), "r"(b[1]));
}
__device__ __forceinline__ uint32_t swz128(uint32_t o) { return o ^ ((o >> 3) & 0x70); }

__device__ __forceinline__ void packh2(float a, float b, uint32_t& r) {
    half2 p; p.x = __float2half_rn(a); p.y = __float2half_rn(b);
    r = *(uint32_t*)&p;
}

// ---------------- weight prep (vectorized transposes) --------------------------
// 3 QKV weights: [H,E,D] -> Bt[n=h*64+d][k=e], single fp16 (3 consecutive slots).
// 32x32 tile; float4 loads, pad-33 smem (conflict-free both phases), 8B stores.
__global__ void __launch_bounds__(256) wqkv_cvt3(
    const float* __restrict__ w0, const float* __restrict__ w1,
    const float* __restrict__ w2, half* __restrict__ o16) {
    __shared__ float tile[32][33];
    int dt = blockIdx.x;            // 0..1 (d tile)
    int et = blockIdx.y;            // 0..31 (e tile)
    int z  = blockIdx.z;            // s*16 + h, s in 0..2
    int s = z >> 4, h = z & 15;
    const float* src = (s == 0) ? w0 : (s == 1 ? w1 : w2);
    int t = threadIdx.x;
    int e0 = et * 32, d0 = dt * 32;
    {
        int e = t >> 3, d4 = (t & 7) << 2;
        float4 v = *(const float4*)(src + (size_t)h * (E_DIM * D_DIM)
                                    + (size_t)(e0 + e) * D_DIM + d0 + d4);
        tile[e][d4 + 0] = v.x; tile[e][d4 + 1] = v.y;
        tile[e][d4 + 2] = v.z; tile[e][d4 + 3] = v.w;
    }
    __syncthreads();
    {
        int d = t >> 3, e4 = (t & 7) << 2;
        uint32_t lo, hi;
        packh2(tile[e4 + 0][d], tile[e4 + 1][d], lo);
        packh2(tile[e4 + 2][d], tile[e4 + 3][d], hi);
        uint2 pk; pk.x = lo; pk.y = hi;
        size_t oidx = (size_t)s * MB1 + (size_t)(h * 64 + d0 + d) * E_DIM + e0 + e4;
        *(uint2*)(o16 + oidx) = pk;
    }
}
// [K,N] row-major -> Bt[n][k], single fp16 (vectorized)
__global__ void __launch_bounds__(256) wt_cvt16(const float* __restrict__ src,
                                                half* __restrict__ o16, int K, int N) {
    __shared__ float tile[32][33];
    int n0 = blockIdx.x * 32, k0 = blockIdx.y * 32;
    int t = threadIdx.x;
    {
        int k = t >> 3, n4 = (t & 7) << 2;
        float4 v = *(const float4*)(src + (size_t)(k0 + k) * N + n0 + n4);
        tile[k][n4 + 0] = v.x; tile[k][n4 + 1] = v.y;
        tile[k][n4 + 2] = v.z; tile[k][n4 + 3] = v.w;
    }
    __syncthreads();
    {
        int n = t >> 3, k4 = (t & 7) << 2;
        uint32_t lo, hi;
        packh2(tile[k4 + 0][n], tile[k4 + 1][n], lo);
        packh2(tile[k4 + 2][n], tile[k4 + 3][n], hi);
        uint2 pk; pk.x = lo; pk.y = hi;
        *(uint2*)(o16 + (size_t)(n0 + n) * K + k0 + k4) = pk;
    }
}
// f32 -> single fp16
__global__ void cvt16(const float* __restrict__ src, half* __restrict__ dst) {
    int i = blockIdx.x * 256 + threadIdx.x;
    float4 v = ((const float4*)src)[i];
    uint32_t p0, p1;
    packh2(v.x, v.y, p0);
    packh2(v.z, v.w, p1);
    *(uint32_t*)(dst + 4 * (size_t)i) = p0;
    *(uint32_t*)(dst + 4 * (size_t)i + 2) = p1;
}

// ---------------- LayerNorm: f32 -> single fp16, 2 rows per block --------------
__global__ void __launch_bounds__(256) ln_kernel(const float* __restrict__ x,
                                                 const float* __restrict__ g,
                                                 const float* __restrict__ b,
                                                 half* __restrict__ o16) {
    int row0 = blockIdx.x * 2;
    int t = threadIdx.x;
    const float4* xr = (const float4*)(x + (size_t)row0 * E_DIM);
    float4 va = xr[t];          // row0
    float4 vb = xr[256 + t];    // row0 + 1 (E_DIM/4 == 256)
    float sa = va.x + va.y + va.z + va.w;
    float qa = va.x * va.x + va.y * va.y + va.z * va.z + va.w * va.w;
    float sbv = vb.x + vb.y + vb.z + vb.w;
    float qb = vb.x * vb.x + vb.y * vb.y + vb.z * vb.z + vb.w * vb.w;
    #pragma unroll
    for (int o = 16; o > 0; o >>= 1) {
        sa  += __shfl_xor_sync(0xffffffffu, sa, o);
        qa  += __shfl_xor_sync(0xffffffffu, qa, o);
        sbv += __shfl_xor_sync(0xffffffffu, sbv, o);
        qb  += __shfl_xor_sync(0xffffffffu, qb, o);
    }
    __shared__ float red[4][8];
    int w = t >> 5, lane = t & 31;
    if (lane == 0) { red[0][w] = sa; red[1][w] = qa; red[2][w] = sbv; red[3][w] = qb; }
    __syncthreads();
    sa = 0.0f; qa = 0.0f; sbv = 0.0f; qb = 0.0f;
    #pragma unroll
    for (int i = 0; i < 8; i++) {
        sa += red[0][i]; qa += red[1][i]; sbv += red[2][i]; qb += red[3][i];
    }
    float mua  = sa * (1.0f / E_DIM);
    float inva = rsqrtf(qa * (1.0f / E_DIM) - mua * mua + 1e-5f);
    float mub  = sbv * (1.0f / E_DIM);
    float invb = rsqrtf(qb * (1.0f / E_DIM) - mub * mub + 1e-5f);
    float4 gv = ((const float4*)g)[t];
    float4 bv = ((const float4*)b)[t];
    size_t base = (size_t)row0 * E_DIM + t * 4;
    uint32_t p0, p1;
    packh2((va.x - mua) * inva * gv.x + bv.x, (va.y - mua) * inva * gv.y + bv.y, p0);
    packh2((va.z - mua) * inva * gv.z + bv.z, (va.w - mua) * inva * gv.w + bv.w, p1);
    *(uint32_t*)(o16 + base) = p0;
    *(uint32_t*)(o16 + base + 2) = p1;
    packh2((vb.x - mub) * invb * gv.x + bv.x, (vb.y - mub) * invb * gv.y + bv.y, p0);
    packh2((vb.z - mub) * invb * gv.z + bv.z, (vb.w - mub) * invb * gv.w + bv.w, p1);
    *(uint32_t*)(o16 + base + E_DIM) = p0;
    *(uint32_t*)(o16 + base + E_DIM + 2) = p1;
}

#define G16_STAGE 32768
#define G16_SMEM (2 * G16_STAGE + 256)

// ---------------- fp16 GEMM (single x single), 2-stage --------------------------
// EPI: 0 bias -> fp16 single, 1 bias+GELU -> fp16, 2 bias+res -> f32
template <int EPI>
__global__ void __launch_bounds__(128, 2) gemm16(
    const half* __restrict__ A, const half* __restrict__ B,
    const float* __restrict__ bias, const float* __restrict__ res,
    float* __restrict__ outF, half* __restrict__ outH,
    int M, int N, int K) {
    extern __shared__ char dyn[];
    uint32_t sb = (smem_u32(dyn) + 127) & ~127u;
    int tid = threadIdx.x, lane = tid & 31, wid = tid >> 5;
    int rBase = blockIdx.y * 128, cBase = blockIdx.x * 128;
    int m0 = (wid >> 1) * 64, n0 = (wid & 1) * 64;

    float acc[4][8][4];
    #pragma unroll
    for (int i = 0; i < 4; i++)
        #pragma unroll
        for (int j = 0; j < 8; j++)
            #pragma unroll
            for (int u = 0; u < 4; u++) acc[i][j][u] = 0.0f;

    const int nc = K >> 6;
    auto loadStage = [&](int s, int c) {
        uint32_t base = sb + s * G16_STAGE;
        int k0 = c << 6;
        #pragma unroll
        for (int i = 0; i < 8; i++) {
            int idx = i * 128 + tid;
            int row = idx >> 3, c16 = idx & 7;
            uint32_t off = swz128(row * 128 + c16 * 16);
            cpasync16(base + off,         A + (size_t)(rBase + row) * K + k0 + c16 * 8);
            cpasync16(base + 16384 + off, B + (size_t)(cBase + row) * K + k0 + c16 * 8);
        }
    };

    int aRow = (lane & 7) + ((lane >> 3) & 1) * 8;
    int aC   = lane >> 4;
    int bRow16 = (lane & 7) + ((lane >> 4) & 1) * 8;
    int bH     = (lane >> 3) & 1;

    loadStage(0, 0); cpcommit();

    for (int c = 0; c < nc; c++) {
        if (c + 1 < nc) { loadStage((c + 1) & 1, c + 1); cpcommit(); cpwait<1>(); }
        else            { cpwait<0>(); }
        __syncthreads();
        uint32_t base = sb + (c & 1) * G16_STAGE;
        #pragma unroll
        for (int kc = 0; kc < 4; kc++) {
            uint32_t bh[8][2];
            #pragma unroll
            for (int jp = 0; jp < 4; jp++) {
                int row = n0 + jp * 16 + bRow16;
                uint32_t t4[4];
                ldsm4(t4, base + 16384 + swz128(row * 128 + kc * 32 + bH * 16));
                bh[2 * jp][0] = t4[0]; bh[2 * jp][1] = t4[1];
                bh[2 * jp + 1][0] = t4[2]; bh[2 * jp + 1][1] = t4[3];
            }
            #pragma unroll
            for (int i = 0; i < 4; i++) {
                uint32_t a4[4];
                int row = m0 + i * 16 + aRow;
                ldsm4(a4, base + swz128(row * 128 + kc * 32 + aC * 16));
                #pragma unroll
                for (int j = 0; j < 8; j++)
                    mma16816h(acc[i][j], a4, bh[j]);
            }
        }
        __syncthreads();
    }

    int lr = lane >> 2, lc = (lane & 3) << 1;
    #pragma unroll
    for (int i = 0; i < 4; i++) {
        #pragma unroll
        for (int half_ = 0; half_ < 2; half_++) {
            size_t row = (size_t)(rBase + m0 + i * 16 + lr + half_ * 8);
            #pragma unroll
            for (int j = 0; j < 8; j++) {
                int col = cBase + n0 + j * 8 + lc;
                float v0 = acc[i][j][half_ * 2 + 0] + bias[col];
                float v1 = acc[i][j][half_ * 2 + 1] + bias[col + 1];
                if (EPI == 0) {
                    uint32_t p;
                    packh2(v0, v1, p);
                    *(uint32_t*)(outH + row * N + col) = p;
                } else if (EPI == 1) {
                    v0 = 0.5f * v0 * (1.0f + erff(v0 * 0.70710678118654752f));
                    v1 = 0.5f * v1 * (1.0f + erff(v1 * 0.70710678118654752f));
                    uint32_t p;
                    packh2(v0, v1, p);
                    *(uint32_t*)(outH + row * N + col) = p;
                } else {
                    float2 rv = *(const float2*)(res + row * N + col);
                    float2 o; o.x = v0 + rv.x; o.y = v1 + rv.y;
                    *(float2*)(outF + row * N + col) = o;
                }
            }
        }
    }
}

// ---------------- fused QKV / KV projection GEMM (2-stage) ----------------------
// MODE 0 (N=3072): region r -> out[r] with bias[r]  (Q, K, V — all single fp16)
// MODE 1 (N=2048): region 0 -> o1/b1 (K), region 1 -> o2/b2 (V)
template <int MODE>
__global__ void __launch_bounds__(128, 2) gemm_qkv(
    const half* __restrict__ A, const half* __restrict__ B,
    const float* __restrict__ b0, const float* __restrict__ b1,
    const float* __restrict__ b2,
    half* __restrict__ o0, half* __restrict__ o1, half* __restrict__ o2,
    int M, int K) {
    extern __shared__ char dyn[];
    uint32_t sb = (smem_u32(dyn) + 127) & ~127u;
    int tid = threadIdx.x, lane = tid & 31, wid = tid >> 5;
    int rBase = blockIdx.y * 128, cBase = blockIdx.x * 128;
    int m0 = (wid >> 1) * 64, n0 = (wid & 1) * 64;

    float acc[4][8][4];
    #pragma unroll
    for (int i = 0; i < 4; i++)
        #pragma unroll
        for (int j = 0; j < 8; j++)
            #pragma unroll
            for (int u = 0; u < 4; u++) acc[i][j][u] = 0.0f;

    const int nc = K >> 6;
    auto loadStage = [&](int s, int c) {
        uint32_t base = sb + s * G16_STAGE;
        int k0 = c << 6;
        #pragma unroll
        for (int i = 0; i < 8; i++) {
            int idx = i * 128 + tid;
            int row = idx >> 3, c16 = idx & 7;
            uint32_t off = swz128(row * 128 + c16 * 16);
            cpasync16(base + off,         A + (size_t)(rBase + row) * K + k0 + c16 * 8);
            cpasync16(base + 16384 + off, B + (size_t)(cBase + row) * K + k0 + c16 * 8);
        }
    };

    int aRow = (lane & 7) + ((lane >> 3) & 1) * 8;
    int aC   = lane >> 4;
    int bRow16 = (lane & 7) + ((lane >> 4) & 1) * 8;
    int bH     = (lane >> 3) & 1;

    loadStage(0, 0); cpcommit();

    for (int c = 0; c < nc; c++) {
        if (c + 1 < nc) { loadStage((c + 1) & 1, c + 1); cpcommit(); cpwait<1>(); }
        else            { cpwait<0>(); }
        __syncthreads();
        uint32_t base = sb + (c & 1) * G16_STAGE;
        #pragma unroll
        for (int kc = 0; kc < 4; kc++) {
            uint32_t bh[8][2];
            #pragma unroll
            for (int jp = 0; jp < 4; jp++) {
                int row = n0 + jp * 16 + bRow16;
                uint32_t t4[4];
                ldsm4(t4, base + 16384 + swz128(row * 128 + kc * 32 + bH * 16));
                bh[2 * jp][0] = t4[0]; bh[2 * jp][1] = t4[1];
                bh[2 * jp + 1][0] = t4[2]; bh[2 * jp + 1][1] = t4[3];
            }
            #pragma unroll
            for (int i = 0; i < 4; i++) {
                uint32_t a4[4];
                int row = m0 + i * 16 + aRow;
                ldsm4(a4, base + swz128(row * 128 + kc * 32 + aC * 16));
                #pragma unroll
                for (int j = 0; j < 8; j++)
                    mma16816h(acc[i][j], a4, bh[j]);
            }
        }
        __syncthreads();
    }

    int region = cBase >> 10;
    int cLoc = (cBase & 1023) + n0;
    const float* bias;
    half* outS;
    if (MODE == 0) {
        bias = (region == 0) ? b0 : (region == 1 ? b1 : b2);
        outS = (region == 0) ? o0 : (region == 1 ? o1 : o2);
    } else {
        bias = (region == 0) ? b1 : b2;
        outS = (region == 0) ? o1 : o2;
    }

    int lr = lane >> 2, lc = (lane & 3) << 1;
    #pragma unroll
    for (int i = 0; i < 4; i++) {
        #pragma unroll
        for (int half_ = 0; half_ < 2; half_++) {
            size_t row = (size_t)(rBase + m0 + i * 16 + lr + half_ * 8);
            #pragma unroll
            for (int j = 0; j < 8; j++) {
                int col = cLoc + j * 8 + lc;
                float v0 = acc[i][j][half_ * 2 + 0] + bias[col];
                float v1 = acc[i][j][half_ * 2 + 1] + bias[col + 1];
                uint32_t p;
                packh2(v0, v1, p);
                *(uint32_t*)(outS + row * E_DIM + col) = p;
            }
        }
    }
}

// ---------------- flash attention (D=64): all-single fp16, 2-stage -------------
// grid (S/64, H, B), 128 threads, 4 CTAs/SM.
// SMEM: Q 8K @0 | stage s at 8K + s*16K: K (8K), V (8K).
#define ATTN_SMEM (8192 + 2 * 16384 + 1024)
template <bool CAUSAL>
__global__ void __launch_bounds__(128, 4) attn16(
    const half* __restrict__ Q, const half* __restrict__ K,
    const half* __restrict__ V, half* __restrict__ O) {
    extern __shared__ char dyn[];
    uint32_t sb = (smem_u32(dyn) + 1023) & ~1023u;
    int tid = threadIdx.x, lane = tid & 31, w = tid >> 5;
    int b = blockIdx.z, hh = blockIdx.y;
    int qt = CAUSAL ? ((int)gridDim.x - 1 - (int)blockIdx.x) : (int)blockIdx.x;
    size_t headOff = (size_t)hh * D_DIM;
    size_t tokBase = (size_t)b * S_LEN;

    int aRow = (lane & 7) + ((lane >> 3) & 1) * 8;
    int aC = lane >> 4;

    {
        #pragma unroll
        for (int i = 0; i < 4; i++) {
            int idx = i * 128 + tid;
            int r = idx >> 3, c = idx & 7;
            uint32_t off = swz128(r * 128 + c * 16);
            cpasync16(sb + off, Q + (tokBase + qt * 64 + r) * E_DIM + headOff + c * 8);
        }
    }
    auto loadKV = [&](int s, int kt) {
        uint32_t base = sb + 8192 + s * 16384;
        #pragma unroll
        for (int i = 0; i < 4; i++) {
            int idx = i * 128 + tid;
            int r = idx >> 3, c = idx & 7;
            uint32_t off = swz128(r * 128 + c * 16);
            size_t src = (tokBase + kt * 64 + r) * E_DIM + headOff + c * 8;
            cpasync16(base + off,        K + src);
            cpasync16(base + 8192 + off, V + src);
        }
    };
    loadKV(0, 0);
    cpcommit();

    uint32_t qf[4][4];
    float oacc[8][4];
    float mrow[2] = {-1e30f, -1e30f}, lrow[2] = {0.0f, 0.0f};
    #pragma unroll
    for (int j = 0; j < 8; j++)
        #pragma unroll
        for (int u = 0; u < 4; u++) oacc[j][u] = 0.0f;

    const int ntiles = CAUSAL ? (qt + 1) : (S_LEN / 64);
    for (int kt = 0; kt < ntiles; kt++) {
        if (kt + 1 < ntiles) { loadKV((kt + 1) & 1, kt + 1); cpcommit(); cpwait<1>(); }
        else                 { cpwait<0>(); }
        __syncthreads();
        if (kt == 0) {
            #pragma unroll
            for (int s = 0; s < 4; s++)
                ldsm4(qf[s], sb + swz128((w * 16 + aRow) * 128 + s * 32 + aC * 16));
        }
        uint32_t kb = sb + 8192 + (kt & 1) * 16384;
        uint32_t vb = kb + 8192;

        float sacc[8][4];
        #pragma unroll
        for (int j = 0; j < 8; j++)
            #pragma unroll
            for (int u = 0; u < 4; u++) sacc[j][u] = 0.0f;
        #pragma unroll
        for (int s = 0; s < 4; s++) {
            #pragma unroll
            for (int jp = 0; jp < 4; jp++) {
                uint32_t k4[4];
                ldsm4(k4, kb + swz128((jp * 16 + aRow) * 128 + s * 32 + aC * 16));
                uint32_t b0[2] = {k4[0], k4[2]}, b1[2] = {k4[1], k4[3]};
                mma16816h(sacc[2 * jp],     qf[s], b0);
                mma16816h(sacc[2 * jp + 1], qf[s], b1);
            }
        }

        if (CAUSAL && kt == qt) {
            int ql0 = w * 16 + (lane >> 2);
            #pragma unroll
            for (int j = 0; j < 8; j++)
                #pragma unroll
                for (int u = 0; u < 4; u++) {
                    int kcol = j * 8 + ((lane & 3) << 1) + (u & 1);
                    int qrow = ql0 + (u >> 1) * 8;
                    if (kcol > qrow) sacc[j][u] = -1e30f;
                }
        }

        #pragma unroll
        for (int h2 = 0; h2 < 2; h2++) {
            float mt = -1e30f;
            #pragma unroll
            for (int j = 0; j < 8; j++)
                mt = fmaxf(mt, fmaxf(sacc[j][2 * h2], sacc[j][2 * h2 + 1]));
            mt = fmaxf(mt, __shfl_xor_sync(0xffffffffu, mt, 1));
            mt = fmaxf(mt, __shfl_xor_sync(0xffffffffu, mt, 2));
            float mn = fmaxf(mrow[h2], mt);
            float sc = __expf(mrow[h2] - mn);
            mrow[h2] = mn;
            float ts = 0.0f;
            #pragma unroll
            for (int j = 0; j < 8; j++) {
                sacc[j][2 * h2]     = __expf(sacc[j][2 * h2] - mn);
                sacc[j][2 * h2 + 1] = __expf(sacc[j][2 * h2 + 1] - mn);
                ts += sacc[j][2 * h2] + sacc[j][2 * h2 + 1];
            }
            ts += __shfl_xor_sync(0xffffffffu, ts, 1);
            ts += __shfl_xor_sync(0xffffffffu, ts, 2);
            lrow[h2] = lrow[h2] * sc + ts;
            #pragma unroll
            for (int j = 0; j < 8; j++) {
                oacc[j][2 * h2]     *= sc;
                oacc[j][2 * h2 + 1] *= sc;
            }
        }

        #pragma unroll
        for (int s = 0; s < 4; s++) {
            uint32_t pf[4];
            packh2(sacc[2 * s][0],     sacc[2 * s][1],     pf[0]);
            packh2(sacc[2 * s][2],     sacc[2 * s][3],     pf[1]);
            packh2(sacc[2 * s + 1][0], sacc[2 * s + 1][1], pf[2]);
            packh2(sacc[2 * s + 1][2], sacc[2 * s + 1][3], pf[3]);
            #pragma unroll
            for (int jp = 0; jp < 4; jp++) {
                uint32_t v4[4];
                ldsm4t(v4, vb + swz128((s * 16 + aRow) * 128 + jp * 32 + aC * 16));
                uint32_t b0[2] = {v4[0], v4[1]}, b1[2] = {v4[2], v4[3]};
                mma16816h(oacc[2 * jp],     pf, b0);
                mma16816h(oacc[2 * jp + 1], pf, b1);
            }
        }
        __syncthreads();
    }

    #pragma unroll
    for (int h2 = 0; h2 < 2; h2++) {
        float inv = 1.0f / lrow[h2];
        int trow = qt * 64 + w * 16 + (lane >> 2) + h2 * 8;
        size_t rp = (tokBase + trow) * E_DIM + headOff;
        #pragma unroll
        for (int j = 0; j < 8; j++) {
            uint32_t p;
            packh2(oacc[j][2 * h2] * inv, oacc[j][2 * h2 + 1] * inv, p);
            int col = j * 8 + ((lane & 3) << 1);
            *(uint32_t*)(O + rp + col) = p;
        }
    }
}

// ---------------- launch ------------------------------------------------------
extern "C" void kernel_launch(void* const* d_in, const int* in_sizes, int n_in,
                              void* d_out, int out_size) {
    const float* x    = (const float*)d_in[0];
    const float* enc  = (const float*)d_in[1];
    const float* ln1g = (const float*)d_in[2];
    const float* ln1b = (const float*)d_in[3];
    const float* ln2g = (const float*)d_in[4];
    const float* ln2b = (const float*)d_in[5];
    const float* ln3g = (const float*)d_in[6];
    const float* ln3b = (const float*)d_in[7];
    const float* Wq1  = (const float*)d_in[8];
    const float* bq1  = (const float*)d_in[9];
    const float* Wk1  = (const float*)d_in[10];
    const float* bk1  = (const float*)d_in[11];
    const float* Wv1  = (const float*)d_in[12];
    const float* bv1  = (const float*)d_in[13];
    const float* Wo1  = (const float*)d_in[14];
    const float* bo1  = (const float*)d_in[15];
    const float* Wq2  = (const float*)d_in[16];
    const float* bq2  = (const float*)d_in[17];
    const float* Wk2  = (const float*)d_in[18];
    const float* bk2  = (const float*)d_in[19];
    const float* Wv2  = (const float*)d_in[20];
    const float* bv2  = (const float*)d_in[21];
    const float* Wo2  = (const float*)d_in[22];
    const float* bo2  = (const float*)d_in[23];
    const float* Wup  = (const float*)d_in[24];
    const float* bup  = (const float*)d_in[25];
    const float* Wdn  = (const float*)d_in[26];
    const float* bdn  = (const float*)d_in[27];
    float* out = (float*)d_out;

    half *W16, *h16, *e16, *q16, *k16, *v16, *k2, *v2, *a16;
    float *x1, *x2;
    cudaGetSymbolAddress((void**)&W16, g_W16);
    cudaGetSymbolAddress((void**)&h16, g_h16);
    cudaGetSymbolAddress((void**)&e16, g_e16);
    cudaGetSymbolAddress((void**)&q16, g_q16);
    cudaGetSymbolAddress((void**)&k16, g_k16);
    cudaGetSymbolAddress((void**)&v16, g_v16);
    cudaGetSymbolAddress((void**)&k2,  g_k2);
    cudaGetSymbolAddress((void**)&v2,  g_v2);
    cudaGetSymbolAddress((void**)&a16, g_a16);
    cudaGetSymbolAddress((void**)&x1,  g_x1);
    cudaGetSymbolAddress((void**)&x2,  g_x2);

    cudaFuncSetAttribute(gemm16<0>, cudaFuncAttributeMaxDynamicSharedMemorySize, G16_SMEM);
    cudaFuncSetAttribute(gemm16<1>, cudaFuncAttributeMaxDynamicSharedMemorySize, G16_SMEM);
    cudaFuncSetAttribute(gemm16<2>, cudaFuncAttributeMaxDynamicSharedMemorySize, G16_SMEM);
    cudaFuncSetAttribute(gemm_qkv<0>, cudaFuncAttributeMaxDynamicSharedMemorySize, G16_SMEM);
    cudaFuncSetAttribute(gemm_qkv<1>, cudaFuncAttributeMaxDynamicSharedMemorySize, G16_SMEM);
    cudaFuncSetAttribute(attn16<true>,  cudaFuncAttributeMaxDynamicSharedMemorySize, ATTN_SMEM);
    cudaFuncSetAttribute(attn16<false>, cudaFuncAttributeMaxDynamicSharedMemorySize, ATTN_SMEM);

    static cudaStream_t sPrep = nullptr;
    static cudaEvent_t eFork, eQKV1W, eQKV2W, eKV2, eWo1, eWo2, eWup, eWdn;
    if (sPrep == nullptr) {
        cudaStreamCreateWithFlags(&sPrep, cudaStreamNonBlocking);
        cudaEventCreateWithFlags(&eFork,  cudaEventDisableTiming);
        cudaEventCreateWithFlags(&eQKV1W, cudaEventDisableTiming);
        cudaEventCreateWithFlags(&eQKV2W, cudaEventDisableTiming);
        cudaEventCreateWithFlags(&eKV2,   cudaEventDisableTiming);
        cudaEventCreateWithFlags(&eWo1,   cudaEventDisableTiming);
        cudaEventCreateWithFlags(&eWo2,   cudaEventDisableTiming);
        cudaEventCreateWithFlags(&eWup,   cudaEventDisableTiming);
        cudaEventCreateWithFlags(&eWdn,   cudaEventDisableTiming);
    }

    const int WS = E_DIM * E_DIM;
    dim3 gSq(8, 32);
    dim3 gUp(32, 32);
    dim3 gQKV(24, 32);
    dim3 gKV(16, 32);
    dim3 gAttn(S_LEN / 64, H_NUM, B_NUM);

    // ---- fork prep stream ----
    cudaEventRecord(eFork, 0);
    cudaStreamWaitEvent(sPrep, eFork, 0);
    wqkv_cvt3<<<dim3(2, 32, 48), 256, 0, sPrep>>>(Wq1, Wk1, Wv1, W16);            // slots 0-2
    cudaEventRecord(eQKV1W, sPrep);
    wqkv_cvt3<<<dim3(2, 32, 48), 256, 0, sPrep>>>(Wq2, Wk2, Wv2, W16 + 3 * WS);   // slots 3-5
    cudaEventRecord(eQKV2W, sPrep);
    cvt16<<<4096, 256, 0, sPrep>>>(enc, e16);
    wt_cvt16<<<dim3(32, 32), 256, 0, sPrep>>>(Wo1, W16 + 6 * WS, 1024, 1024);
    cudaEventRecord(eWo1, sPrep);
    // KV2 projection — depends only on enc + slots 4-5; co-runs with block 1.
    gemm_qkv<1><<<gKV, 128, G16_SMEM, sPrep>>>(e16, W16 + 4 * WS, nullptr, bk2, bv2,
                                               nullptr, k2, v2, M_ROWS, E_DIM);
    cudaEventRecord(eKV2, sPrep);
    wt_cvt16<<<dim3(32, 32), 256, 0, sPrep>>>(Wo2, W16 + 7 * WS, 1024, 1024);
    cudaEventRecord(eWo2, sPrep);
    wt_cvt16<<<dim3(128, 32), 256, 0, sPrep>>>(Wup, W16 + 8 * WS, 1024, 4096);
    cudaEventRecord(eWup, sPrep);
    wt_cvt16<<<dim3(32, 128), 256, 0, sPrep>>>(Wdn, W16 + 12 * WS, 4096, 1024);
    cudaEventRecord(eWdn, sPrep);

    // ---- main chain ----
    ln_kernel<<<M_ROWS / 2, 256>>>(x, ln1g, ln1b, h16);
    cudaStreamWaitEvent(0, eQKV1W, 0);
    gemm_qkv<0><<<gQKV, 128, G16_SMEM>>>(h16, W16, bq1, bk1, bv1,
                                         q16, k16, v16, M_ROWS, E_DIM);
    attn16<true><<<gAttn, 128, ATTN_SMEM>>>(q16, k16, v16, a16);
    cudaStreamWaitEvent(0, eWo1, 0);
    gemm16<2><<<gSq, 128, G16_SMEM>>>(a16, W16 + 6 * WS, bo1, x,
                                      x1, nullptr, M_ROWS, E_DIM, E_DIM);

    ln_kernel<<<M_ROWS / 2, 256>>>(x1, ln2g, ln2b, h16);
    cudaStreamWaitEvent(0, eQKV2W, 0);
    gemm16<0><<<gSq, 128, G16_SMEM>>>(h16, W16 + 3 * WS, bq2, nullptr,
                                      nullptr, q16, M_ROWS, E_DIM, E_DIM);
    cudaStreamWaitEvent(0, eKV2, 0);
    attn16<false><<<gAttn, 128, ATTN_SMEM>>>(q16, k2, v2, a16);
    cudaStreamWaitEvent(0, eWo2, 0);
    gemm16<2><<<gSq, 128, G16_SMEM>>>(a16, W16 + 7 * WS, bo2, x1,
                                      x2, nullptr, M_ROWS, E_DIM, E_DIM);

    ln_kernel<<<M_ROWS / 2, 256>>>(x2, ln3g, ln3b, h16);
    cudaStreamWaitEvent(0, eWup, 0);
    gemm16<1><<<gUp, 128, G16_SMEM>>>(h16, W16 + 8 * WS, bup, nullptr,
                                      nullptr, a16, M_ROWS, F_DIM, E_DIM);
    cudaStreamWaitEvent(0, eWdn, 0);
    gemm16<2><<<gSq, 128, G16_SMEM>>>(a16, W16 + 12 * WS, bdn, x2,
                                      out, nullptr, M_ROWS, E_DIM, F_DIM);
}

// round 16
// speedup vs baseline: 1.0206x; 1.0206x over previous
#include <cuda_runtime.h>
#include <cuda_fp16.h>
#include <math.h>
#include <cstdint>

#define E_DIM 1024
#define H_NUM 16
#define D_DIM 64
#define B_NUM 4
#define S_LEN 1024
#define F_DIM 4096
#define M_ROWS (B_NUM * S_LEN)  // 4096
#define MB1 (1024 * 1024)

// ---------------- scratch (static device globals) ---------------------------
// Weight slots (single fp16, [N][K] transposed): QKV1 0-2, QKV2 3-5, Wo1 6, Wo2 7,
// Wup 8-11, Wdn 12-15.
__device__ __align__(16) half g_W16[16 * MB1];
__device__ __align__(16) half g_h16[4 * MB1];          // LN out
__device__ __align__(16) half g_e16[4 * MB1];          // enc
__device__ __align__(16) half g_q16[4 * MB1];          // Q
__device__ __align__(16) half g_k16[4 * MB1];          // K1
__device__ __align__(16) half g_v16[4 * MB1];          // V1
__device__ __align__(16) half g_k2[4 * MB1];           // K2
__device__ __align__(16) half g_v2[4 * MB1];           // V2
__device__ __align__(16) half g_a16[16 * MB1];         // attn out / GELU out
__device__ __align__(16) float g_x1[4 * MB1], g_x2[4 * MB1];

// ---------------- PTX helpers -----------------------------------------------
__device__ __forceinline__ uint32_t smem_u32(const void* p) {
    uint32_t a;
    asm("{ .reg .u64 t; cvta.to.shared.u64 t, %1; cvt.u32.u64 %0, t; }" : "=r"(a) : "l"(p));
    return a;
}
__device__ __forceinline__ void cpasync16(uint32_t dst, const void* src) {
    asm volatile("cp.async.cg.shared.global [%0], [%1], 16;" :: "r"(dst), "l"(src));
}
__device__ __forceinline__ void cpcommit() { asm volatile("cp.async.commit_group;" ::: "memory"); }
template <int N>
__device__ __forceinline__ void cpwait() { asm volatile("cp.async.wait_group %0;" :: "n"(N) : "memory"); }

__device__ __forceinline__ void ldsm4(uint32_t (&r)[4], uint32_t addr) {
    asm volatile("ldmatrix.sync.aligned.m8n8.x4.shared.b16 {%0,%1,%2,%3}, [%4];"
                 : "=r"(r[0]), "=r"(r[1]), "=r"(r[2]), "=r"(r[3]) : "r"(addr));
}
__device__ __forceinline__ void ldsm4t(uint32_t (&r)[4], uint32_t addr) {
    asm volatile("ldmatrix.sync.aligned.m8n8.x4.trans.shared.b16 {%0,%1,%2,%3}, [%4];"
                 : "=r"(r[0]), "=r"(r[1]), "=r"(r[2]), "=r"(r[3]) : "r"(addr));
}
__device__ __forceinline__ void mma16816h(float (&d)[4], const uint32_t (&a)[4],
                                          const uint32_t (&b)[2]) {
    asm volatile(
        "mma.sync.aligned.m16n8k16.row.col.f32.f16.f16.f32 "
        "{%0,%1,%2,%3}, {%4,%5,%6,%7}, {%8,%9}, {%0,%1,%2,%3};"
        : "+f"(d[0]), "+f"(d[1]), "+f"(d[2]), "+f"(d[3])
        : "r"(a[0]), "r"(a[1]), "r"(a[2]), "r"(a[3]), "r"(b[0]), "r"(b[1]));
}
__device__ __forceinline__ uint32_t swz128(uint32_t o) { return o ^ ((o >> 3) & 0x70); }

__device__ __forceinline__ void packh2(float a, float b, uint32_t& r) {
    half2 p; p.x = __float2half_rn(a); p.y = __float2half_rn(b);
    r = *(uint32_t*)&p;
}

// ---------------- weight prep (vectorized transposes) --------------------------
// 3 QKV weights: [H,E,D] -> Bt[n=h*64+d][k=e], single fp16 (3 consecutive slots).
__global__ void __launch_bounds__(256) wqkv_cvt3(
    const float* __restrict__ w0, const float* __restrict__ w1,
    const float* __restrict__ w2, half* __restrict__ o16) {
    __shared__ float tile[32][33];
    int dt = blockIdx.x;            // 0..1 (d tile)
    int et = blockIdx.y;            // 0..31 (e tile)
    int z  = blockIdx.z;            // s*16 + h, s in 0..2
    int s = z >> 4, h = z & 15;
    const float* src = (s == 0) ? w0 : (s == 1 ? w1 : w2);
    int t = threadIdx.x;
    int e0 = et * 32, d0 = dt * 32;
    {
        int e = t >> 3, d4 = (t & 7) << 2;
        float4 v = *(const float4*)(src + (size_t)h * (E_DIM * D_DIM)
                                    + (size_t)(e0 + e) * D_DIM + d0 + d4);
        tile[e][d4 + 0] = v.x; tile[e][d4 + 1] = v.y;
        tile[e][d4 + 2] = v.z; tile[e][d4 + 3] = v.w;
    }
    __syncthreads();
    {
        int d = t >> 3, e4 = (t & 7) << 2;
        uint32_t lo, hi;
        packh2(tile[e4 + 0][d], tile[e4 + 1][d], lo);
        packh2(tile[e4 + 2][d], tile[e4 + 3][d], hi);
        uint2 pk; pk.x = lo; pk.y = hi;
        size_t oidx = (size_t)s * MB1 + (size_t)(h * 64 + d0 + d) * E_DIM + e0 + e4;
        *(uint2*)(o16 + oidx) = pk;
    }
}
// [K,N] row-major -> Bt[n][k], single fp16 (vectorized)
__global__ void __launch_bounds__(256) wt_cvt16(const float* __restrict__ src,
                                                half* __restrict__ o16, int K, int N) {
    __shared__ float tile[32][33];
    int n0 = blockIdx.x * 32, k0 = blockIdx.y * 32;
    int t = threadIdx.x;
    {
        int k = t >> 3, n4 = (t & 7) << 2;
        float4 v = *(const float4*)(src + (size_t)(k0 + k) * N + n0 + n4);
        tile[k][n4 + 0] = v.x; tile[k][n4 + 1] = v.y;
        tile[k][n4 + 2] = v.z; tile[k][n4 + 3] = v.w;
    }
    __syncthreads();
    {
        int n = t >> 3, k4 = (t & 7) << 2;
        uint32_t lo, hi;
        packh2(tile[k4 + 0][n], tile[k4 + 1][n], lo);
        packh2(tile[k4 + 2][n], tile[k4 + 3][n], hi);
        uint2 pk; pk.x = lo; pk.y = hi;
        *(uint2*)(o16 + (size_t)(n0 + n) * K + k0 + k4) = pk;
    }
}
// f32 -> single fp16
__global__ void cvt16(const float* __restrict__ src, half* __restrict__ dst) {
    int i = blockIdx.x * 256 + threadIdx.x;
    float4 v = ((const float4*)src)[i];
    uint32_t p0, p1;
    packh2(v.x, v.y, p0);
    packh2(v.z, v.w, p1);
    *(uint32_t*)(dst + 4 * (size_t)i) = p0;
    *(uint32_t*)(dst + 4 * (size_t)i + 2) = p1;
}

// ---------------- LayerNorm: f32 -> single fp16, 2 rows per block --------------
__global__ void __launch_bounds__(256) ln_kernel(const float* __restrict__ x,
                                                 const float* __restrict__ g,
                                                 const float* __restrict__ b,
                                                 half* __restrict__ o16) {
    int row0 = blockIdx.x * 2;
    int t = threadIdx.x;
    const float4* xr = (const float4*)(x + (size_t)row0 * E_DIM);
    float4 va = xr[t];
    float4 vb = xr[256 + t];
    float sa = va.x + va.y + va.z + va.w;
    float qa = va.x * va.x + va.y * va.y + va.z * va.z + va.w * va.w;
    float sbv = vb.x + vb.y + vb.z + vb.w;
    float qb = vb.x * vb.x + vb.y * vb.y + vb.z * vb.z + vb.w * vb.w;
    #pragma unroll
    for (int o = 16; o > 0; o >>= 1) {
        sa  += __shfl_xor_sync(0xffffffffu, sa, o);
        qa  += __shfl_xor_sync(0xffffffffu, qa, o);
        sbv += __shfl_xor_sync(0xffffffffu, sbv, o);
        qb  += __shfl_xor_sync(0xffffffffu, qb, o);
    }
    __shared__ float red[4][8];
    int w = t >> 5, lane = t & 31;
    if (lane == 0) { red[0][w] = sa; red[1][w] = qa; red[2][w] = sbv; red[3][w] = qb; }
    __syncthreads();
    sa = 0.0f; qa = 0.0f; sbv = 0.0f; qb = 0.0f;
    #pragma unroll
    for (int i = 0; i < 8; i++) {
        sa += red[0][i]; qa += red[1][i]; sbv += red[2][i]; qb += red[3][i];
    }
    float mua  = sa * (1.0f / E_DIM);
    float inva = rsqrtf(qa * (1.0f / E_DIM) - mua * mua + 1e-5f);
    float mub  = sbv * (1.0f / E_DIM);
    float invb = rsqrtf(qb * (1.0f / E_DIM) - mub * mub + 1e-5f);
    float4 gv = ((const float4*)g)[t];
    float4 bv = ((const float4*)b)[t];
    size_t base = (size_t)row0 * E_DIM + t * 4;
    uint32_t p0, p1;
    packh2((va.x - mua) * inva * gv.x + bv.x, (va.y - mua) * inva * gv.y + bv.y, p0);
    packh2((va.z - mua) * inva * gv.z + bv.z, (va.w - mua) * inva * gv.w + bv.w, p1);
    *(uint32_t*)(o16 + base) = p0;
    *(uint32_t*)(o16 + base + 2) = p1;
    packh2((vb.x - mub) * invb * gv.x + bv.x, (vb.y - mub) * invb * gv.y + bv.y, p0);
    packh2((vb.z - mub) * invb * gv.z + bv.z, (vb.w - mub) * invb * gv.w + bv.w, p1);
    *(uint32_t*)(o16 + base + E_DIM) = p0;
    *(uint32_t*)(o16 + base + E_DIM + 2) = p1;
}

#define G16_STAGE 32768
#define G16_SMEM (2 * G16_STAGE + 256)

// ---------------- fp16 GEMM (single x single), 2-stage --------------------------
// EPI: 0 bias -> fp16 single, 1 bias+GELU -> fp16, 2 bias+res -> f32
template <int EPI>
__global__ void __launch_bounds__(128, 2) gemm16(
    const half* __restrict__ A, const half* __restrict__ B,
    const float* __restrict__ bias, const float* __restrict__ res,
    float* __restrict__ outF, half* __restrict__ outH,
    int M, int N, int K) {
    extern __shared__ char dyn[];
    uint32_t sb = (smem_u32(dyn) + 127) & ~127u;
    int tid = threadIdx.x, lane = tid & 31, wid = tid >> 5;
    int rBase = blockIdx.y * 128, cBase = blockIdx.x * 128;
    int m0 = (wid >> 1) * 64, n0 = (wid & 1) * 64;

    float acc[4][8][4];
    #pragma unroll
    for (int i = 0; i < 4; i++)
        #pragma unroll
        for (int j = 0; j < 8; j++)
            #pragma unroll
            for (int u = 0; u < 4; u++) acc[i][j][u] = 0.0f;

    const int nc = K >> 6;
    auto loadStage = [&](int s, int c) {
        uint32_t base = sb + s * G16_STAGE;
        int k0 = c << 6;
        #pragma unroll
        for (int i = 0; i < 8; i++) {
            int idx = i * 128 + tid;
            int row = idx >> 3, c16 = idx & 7;
            uint32_t off = swz128(row * 128 + c16 * 16);
            cpasync16(base + off,         A + (size_t)(rBase + row) * K + k0 + c16 * 8);
            cpasync16(base + 16384 + off, B + (size_t)(cBase + row) * K + k0 + c16 * 8);
        }
    };

    int aRow = (lane & 7) + ((lane >> 3) & 1) * 8;
    int aC   = lane >> 4;
    int bRow16 = (lane & 7) + ((lane >> 4) & 1) * 8;
    int bH     = (lane >> 3) & 1;

    loadStage(0, 0); cpcommit();

    for (int c = 0; c < nc; c++) {
        if (c + 1 < nc) { loadStage((c + 1) & 1, c + 1); cpcommit(); cpwait<1>(); }
        else            { cpwait<0>(); }
        __syncthreads();
        uint32_t base = sb + (c & 1) * G16_STAGE;
        #pragma unroll
        for (int kc = 0; kc < 4; kc++) {
            uint32_t bh[8][2];
            #pragma unroll
            for (int jp = 0; jp < 4; jp++) {
                int row = n0 + jp * 16 + bRow16;
                uint32_t t4[4];
                ldsm4(t4, base + 16384 + swz128(row * 128 + kc * 32 + bH * 16));
                bh[2 * jp][0] = t4[0]; bh[2 * jp][1] = t4[1];
                bh[2 * jp + 1][0] = t4[2]; bh[2 * jp + 1][1] = t4[3];
            }
            #pragma unroll
            for (int i = 0; i < 4; i++) {
                uint32_t a4[4];
                int row = m0 + i * 16 + aRow;
                ldsm4(a4, base + swz128(row * 128 + kc * 32 + aC * 16));
                #pragma unroll
                for (int j = 0; j < 8; j++)
                    mma16816h(acc[i][j], a4, bh[j]);
            }
        }
        __syncthreads();
    }

    int lr = lane >> 2, lc = (lane & 3) << 1;
    #pragma unroll
    for (int i = 0; i < 4; i++) {
        #pragma unroll
        for (int half_ = 0; half_ < 2; half_++) {
            size_t row = (size_t)(rBase + m0 + i * 16 + lr + half_ * 8);
            #pragma unroll
            for (int j = 0; j < 8; j++) {
                int col = cBase + n0 + j * 8 + lc;
                float v0 = acc[i][j][half_ * 2 + 0] + bias[col];
                float v1 = acc[i][j][half_ * 2 + 1] + bias[col + 1];
                if (EPI == 0) {
                    uint32_t p;
                    packh2(v0, v1, p);
                    *(uint32_t*)(outH + row * N + col) = p;
                } else if (EPI == 1) {
                    v0 = 0.5f * v0 * (1.0f + erff(v0 * 0.70710678118654752f));
                    v1 = 0.5f * v1 * (1.0f + erff(v1 * 0.70710678118654752f));
                    uint32_t p;
                    packh2(v0, v1, p);
                    *(uint32_t*)(outH + row * N + col) = p;
                } else {
                    float2 rv = *(const float2*)(res + row * N + col);
                    float2 o; o.x = v0 + rv.x; o.y = v1 + rv.y;
                    *(float2*)(outF + row * N + col) = o;
                }
            }
        }
    }
}

// ---------------- fused QKV / KV projection GEMM (2-stage) ----------------------
// MODE 0 (N=3072): region r -> out[r] with bias[r]  (Q, K, V — all single fp16)
// MODE 1 (N=2048): region 0 -> o1/b1 (K), region 1 -> o2/b2 (V)
template <int MODE>
__global__ void __launch_bounds__(128, 2) gemm_qkv(
    const half* __restrict__ A, const half* __restrict__ B,
    const float* __restrict__ b0, const float* __restrict__ b1,
    const float* __restrict__ b2,
    half* __restrict__ o0, half* __restrict__ o1, half* __restrict__ o2,
    int M, int K) {
    extern __shared__ char dyn[];
    uint32_t sb = (smem_u32(dyn) + 127) & ~127u;
    int tid = threadIdx.x, lane = tid & 31, wid = tid >> 5;
    int rBase = blockIdx.y * 128, cBase = blockIdx.x * 128;
    int m0 = (wid >> 1) * 64, n0 = (wid & 1) * 64;

    float acc[4][8][4];
    #pragma unroll
    for (int i = 0; i < 4; i++)
        #pragma unroll
        for (int j = 0; j < 8; j++)
            #pragma unroll
            for (int u = 0; u < 4; u++) acc[i][j][u] = 0.0f;

    const int nc = K >> 6;
    auto loadStage = [&](int s, int c) {
        uint32_t base = sb + s * G16_STAGE;
        int k0 = c << 6;
        #pragma unroll
        for (int i = 0; i < 8; i++) {
            int idx = i * 128 + tid;
            int row = idx >> 3, c16 = idx & 7;
            uint32_t off = swz128(row * 128 + c16 * 16);
            cpasync16(base + off,         A + (size_t)(rBase + row) * K + k0 + c16 * 8);
            cpasync16(base + 16384 + off, B + (size_t)(cBase + row) * K + k0 + c16 * 8);
        }
    };

    int aRow = (lane & 7) + ((lane >> 3) & 1) * 8;
    int aC   = lane >> 4;
    int bRow16 = (lane & 7) + ((lane >> 4) & 1) * 8;
    int bH     = (lane >> 3) & 1;

    loadStage(0, 0); cpcommit();

    for (int c = 0; c < nc; c++) {
        if (c + 1 < nc) { loadStage((c + 1) & 1, c + 1); cpcommit(); cpwait<1>(); }
        else            { cpwait<0>(); }
        __syncthreads();
        uint32_t base = sb + (c & 1) * G16_STAGE;
        #pragma unroll
        for (int kc = 0; kc < 4; kc++) {
            uint32_t bh[8][2];
            #pragma unroll
            for (int jp = 0; jp < 4; jp++) {
                int row = n0 + jp * 16 + bRow16;
                uint32_t t4[4];
                ldsm4(t4, base + 16384 + swz128(row * 128 + kc * 32 + bH * 16));
                bh[2 * jp][0] = t4[0]; bh[2 * jp][1] = t4[1];
                bh[2 * jp + 1][0] = t4[2]; bh[2 * jp + 1][1] = t4[3];
            }
            #pragma unroll
            for (int i = 0; i < 4; i++) {
                uint32_t a4[4];
                int row = m0 + i * 16 + aRow;
                ldsm4(a4, base + swz128(row * 128 + kc * 32 + aC * 16));
                #pragma unroll
                for (int j = 0; j < 8; j++)
                    mma16816h(acc[i][j], a4, bh[j]);
            }
        }
        __syncthreads();
    }

    int region = cBase >> 10;
    int cLoc = (cBase & 1023) + n0;
    const float* bias;
    half* outS;
    if (MODE == 0) {
        bias = (region == 0) ? b0 : (region == 1 ? b1 : b2);
        outS = (region == 0) ? o0 : (region == 1 ? o1 : o2);
    } else {
        bias = (region == 0) ? b1 : b2;
        outS = (region == 0) ? o1 : o2;
    }

    int lr = lane >> 2, lc = (lane & 3) << 1;
    #pragma unroll
    for (int i = 0; i < 4; i++) {
        #pragma unroll
        for (int half_ = 0; half_ < 2; half_++) {
            size_t row = (size_t)(rBase + m0 + i * 16 + lr + half_ * 8);
            #pragma unroll
            for (int j = 0; j < 8; j++) {
                int col = cLoc + j * 8 + lc;
                float v0 = acc[i][j][half_ * 2 + 0] + bias[col];
                float v1 = acc[i][j][half_ * 2 + 1] + bias[col + 1];
                uint32_t p;
                packh2(v0, v1, p);
                *(uint32_t*)(outS + row * E_DIM + col) = p;
            }
        }
    }
}

// ---------------- flash attention (D=64): all-single fp16, 2-stage -------------
// grid (S/64, H, B), 128 threads, 3 CTAs/SM.
#define ATTN_SMEM (8192 + 2 * 16384 + 1024)
template <bool CAUSAL>
__global__ void __launch_bounds__(128, 3) attn16(
    const half* __restrict__ Q, const half* __restrict__ K,
    const half* __restrict__ V, half* __restrict__ O) {
    extern __shared__ char dyn[];
    uint32_t sb = (smem_u32(dyn) + 1023) & ~1023u;
    int tid = threadIdx.x, lane = tid & 31, w = tid >> 5;
    int b = blockIdx.z, hh = blockIdx.y;
    int qt = CAUSAL ? ((int)gridDim.x - 1 - (int)blockIdx.x) : (int)blockIdx.x;
    size_t headOff = (size_t)hh * D_DIM;
    size_t tokBase = (size_t)b * S_LEN;

    int aRow = (lane & 7) + ((lane >> 3) & 1) * 8;
    int aC = lane >> 4;

    {
        #pragma unroll
        for (int i = 0; i < 4; i++) {
            int idx = i * 128 + tid;
            int r = idx >> 3, c = idx & 7;
            uint32_t off = swz128(r * 128 + c * 16);
            cpasync16(sb + off, Q + (tokBase + qt * 64 + r) * E_DIM + headOff + c * 8);
        }
    }
    auto loadKV = [&](int s, int kt) {
        uint32_t base = sb + 8192 + s * 16384;
        #pragma unroll
        for (int i = 0; i < 4; i++) {
            int idx = i * 128 + tid;
            int r = idx >> 3, c = idx & 7;
            uint32_t off = swz128(r * 128 + c * 16);
            size_t src = (tokBase + kt * 64 + r) * E_DIM + headOff + c * 8;
            cpasync16(base + off,        K + src);
            cpasync16(base + 8192 + off, V + src);
        }
    };
    loadKV(0, 0);
    cpcommit();

    uint32_t qf[4][4];
    float oacc[8][4];
    float mrow[2] = {-1e30f, -1e30f}, lrow[2] = {0.0f, 0.0f};
    #pragma unroll
    for (int j = 0; j < 8; j++)
        #pragma unroll
        for (int u = 0; u < 4; u++) oacc[j][u] = 0.0f;

    const int ntiles = CAUSAL ? (qt + 1) : (S_LEN / 64);
    for (int kt = 0; kt < ntiles; kt++) {
        if (kt + 1 < ntiles) { loadKV((kt + 1) & 1, kt + 1); cpcommit(); cpwait<1>(); }
        else                 { cpwait<0>(); }
        __syncthreads();
        if (kt == 0) {
            #pragma unroll
            for (int s = 0; s < 4; s++)
                ldsm4(qf[s], sb + swz128((w * 16 + aRow) * 128 + s * 32 + aC * 16));
        }
        uint32_t kb = sb + 8192 + (kt & 1) * 16384;
        uint32_t vb = kb + 8192;

        float sacc[8][4];
        #pragma unroll
        for (int j = 0; j < 8; j++)
            #pragma unroll
            for (int u = 0; u < 4; u++) sacc[j][u] = 0.0f;
        #pragma unroll
        for (int s = 0; s < 4; s++) {
            #pragma unroll
            for (int jp = 0; jp < 4; jp++) {
                uint32_t k4[4];
                ldsm4(k4, kb + swz128((jp * 16 + aRow) * 128 + s * 32 + aC * 16));
                uint32_t b0[2] = {k4[0], k4[2]}, b1[2] = {k4[1], k4[3]};
                mma16816h(sacc[2 * jp],     qf[s], b0);
                mma16816h(sacc[2 * jp + 1], qf[s], b1);
            }
        }

        if (CAUSAL && kt == qt) {
            int ql0 = w * 16 + (lane >> 2);
            #pragma unroll
            for (int j = 0; j < 8; j++)
                #pragma unroll
                for (int u = 0; u < 4; u++) {
                    int kcol = j * 8 + ((lane & 3) << 1) + (u & 1);
                    int qrow = ql0 + (u >> 1) * 8;
                    if (kcol > qrow) sacc[j][u] = -1e30f;
                }
        }

        #pragma unroll
        for (int h2 = 0; h2 < 2; h2++) {
            float mt = -1e30f;
            #pragma unroll
            for (int j = 0; j < 8; j++)
                mt = fmaxf(mt, fmaxf(sacc[j][2 * h2], sacc[j][2 * h2 + 1]));
            mt = fmaxf(mt, __shfl_xor_sync(0xffffffffu, mt, 1));
            mt = fmaxf(mt, __shfl_xor_sync(0xffffffffu, mt, 2));
            float mn = fmaxf(mrow[h2], mt);
            float sc = __expf(mrow[h2] - mn);
            mrow[h2] = mn;
            float ts = 0.0f;
            #pragma unroll
            for (int j = 0; j < 8; j++) {
                sacc[j][2 * h2]     = __expf(sacc[j][2 * h2] - mn);
                sacc[j][2 * h2 + 1] = __expf(sacc[j][2 * h2 + 1] - mn);
                ts += sacc[j][2 * h2] + sacc[j][2 * h2 + 1];
            }
            ts += __shfl_xor_sync(0xffffffffu, ts, 1);
            ts += __shfl_xor_sync(0xffffffffu, ts, 2);
            lrow[h2] = lrow[h2] * sc + ts;
            #pragma unroll
            for (int j = 0; j < 8; j++) {
                oacc[j][2 * h2]     *= sc;
                oacc[j][2 * h2 + 1] *= sc;
            }
        }

        #pragma unroll
        for (int s = 0; s < 4; s++) {
            uint32_t pf[4];
            packh2(sacc[2 * s][0],     sacc[2 * s][1],     pf[0]);
            packh2(sacc[2 * s][2],     sacc[2 * s][3],     pf[1]);
            packh2(sacc[2 * s + 1][0], sacc[2 * s + 1][1], pf[2]);
            packh2(sacc[2 * s + 1][2], sacc[2 * s + 1][3], pf[3]);
            #pragma unroll
            for (int jp = 0; jp < 4; jp++) {
                uint32_t v4[4];
                ldsm4t(v4, vb + swz128((s * 16 + aRow) * 128 + jp * 32 + aC * 16));
                uint32_t b0[2] = {v4[0], v4[1]}, b1[2] = {v4[2], v4[3]};
                mma16816h(oacc[2 * jp],     pf, b0);
                mma16816h(oacc[2 * jp + 1], pf, b1);
            }
        }
        __syncthreads();
    }

    #pragma unroll
    for (int h2 = 0; h2 < 2; h2++) {
        float inv = 1.0f / lrow[h2];
        int trow = qt * 64 + w * 16 + (lane >> 2) + h2 * 8;
        size_t rp = (tokBase + trow) * E_DIM + headOff;
        #pragma unroll
        for (int j = 0; j < 8; j++) {
            uint32_t p;
            packh2(oacc[j][2 * h2] * inv, oacc[j][2 * h2 + 1] * inv, p);
            int col = j * 8 + ((lane & 3) << 1);
            *(uint32_t*)(O + rp + col) = p;
        }
    }
}

// ---------------- launch ------------------------------------------------------
extern "C" void kernel_launch(void* const* d_in, const int* in_sizes, int n_in,
                              void* d_out, int out_size) {
    const float* x    = (const float*)d_in[0];
    const float* enc  = (const float*)d_in[1];
    const float* ln1g = (const float*)d_in[2];
    const float* ln1b = (const float*)d_in[3];
    const float* ln2g = (const float*)d_in[4];
    const float* ln2b = (const float*)d_in[5];
    const float* ln3g = (const float*)d_in[6];
    const float* ln3b = (const float*)d_in[7];
    const float* Wq1  = (const float*)d_in[8];
    const float* bq1  = (const float*)d_in[9];
    const float* Wk1  = (const float*)d_in[10];
    const float* bk1  = (const float*)d_in[11];
    const float* Wv1  = (const float*)d_in[12];
    const float* bv1  = (const float*)d_in[13];
    const float* Wo1  = (const float*)d_in[14];
    const float* bo1  = (const float*)d_in[15];
    const float* Wq2  = (const float*)d_in[16];
    const float* bq2  = (const float*)d_in[17];
    const float* Wk2  = (const float*)d_in[18];
    const float* bk2  = (const float*)d_in[19];
    const float* Wv2  = (const float*)d_in[20];
    const float* bv2  = (const float*)d_in[21];
    const float* Wo2  = (const float*)d_in[22];
    const float* bo2  = (const float*)d_in[23];
    const float* Wup  = (const float*)d_in[24];
    const float* bup  = (const float*)d_in[25];
    const float* Wdn  = (const float*)d_in[26];
    const float* bdn  = (const float*)d_in[27];
    float* out = (float*)d_out;

    half *W16, *h16, *e16, *q16, *k16, *v16, *k2, *v2, *a16;
    float *x1, *x2;
    cudaGetSymbolAddress((void**)&W16, g_W16);
    cudaGetSymbolAddress((void**)&h16, g_h16);
    cudaGetSymbolAddress((void**)&e16, g_e16);
    cudaGetSymbolAddress((void**)&q16, g_q16);
    cudaGetSymbolAddress((void**)&k16, g_k16);
    cudaGetSymbolAddress((void**)&v16, g_v16);
    cudaGetSymbolAddress((void**)&k2,  g_k2);
    cudaGetSymbolAddress((void**)&v2,  g_v2);
    cudaGetSymbolAddress((void**)&a16, g_a16);
    cudaGetSymbolAddress((void**)&x1,  g_x1);
    cudaGetSymbolAddress((void**)&x2,  g_x2);

    cudaFuncSetAttribute(gemm16<0>, cudaFuncAttributeMaxDynamicSharedMemorySize, G16_SMEM);
    cudaFuncSetAttribute(gemm16<1>, cudaFuncAttributeMaxDynamicSharedMemorySize, G16_SMEM);
    cudaFuncSetAttribute(gemm16<2>, cudaFuncAttributeMaxDynamicSharedMemorySize, G16_SMEM);
    cudaFuncSetAttribute(gemm_qkv<0>, cudaFuncAttributeMaxDynamicSharedMemorySize, G16_SMEM);
    cudaFuncSetAttribute(gemm_qkv<1>, cudaFuncAttributeMaxDynamicSharedMemorySize, G16_SMEM);
    cudaFuncSetAttribute(attn16<true>,  cudaFuncAttributeMaxDynamicSharedMemorySize, ATTN_SMEM);
    cudaFuncSetAttribute(attn16<false>, cudaFuncAttributeMaxDynamicSharedMemorySize, ATTN_SMEM);

    static cudaStream_t sPrep = nullptr;
    static cudaEvent_t eFork, eQKV1W, eQKV2W, eKV2, eWo1, eWo2, eWup, eWdn;
    if (sPrep == nullptr) {
        cudaStreamCreateWithFlags(&sPrep, cudaStreamNonBlocking);
        cudaEventCreateWithFlags(&eFork,  cudaEventDisableTiming);
        cudaEventCreateWithFlags(&eQKV1W, cudaEventDisableTiming);
        cudaEventCreateWithFlags(&eQKV2W, cudaEventDisableTiming);
        cudaEventCreateWithFlags(&eKV2,   cudaEventDisableTiming);
        cudaEventCreateWithFlags(&eWo1,   cudaEventDisableTiming);
        cudaEventCreateWithFlags(&eWo2,   cudaEventDisableTiming);
        cudaEventCreateWithFlags(&eWup,   cudaEventDisableTiming);
        cudaEventCreateWithFlags(&eWdn,   cudaEventDisableTiming);
    }

    const int WS = E_DIM * E_DIM;
    dim3 gSq(8, 32);
    dim3 gUp(32, 32);
    dim3 gQKV(24, 32);
    dim3 gKV(16, 32);
    dim3 gAttn(S_LEN / 64, H_NUM, B_NUM);

    // ---- fork prep stream (KV2 launched as early as deps allow) ----
    cudaEventRecord(eFork, 0);
    cudaStreamWaitEvent(sPrep, eFork, 0);
    wqkv_cvt3<<<dim3(2, 32, 48), 256, 0, sPrep>>>(Wq1, Wk1, Wv1, W16);            // slots 0-2
    cudaEventRecord(eQKV1W, sPrep);
    wqkv_cvt3<<<dim3(2, 32, 48), 256, 0, sPrep>>>(Wq2, Wk2, Wv2, W16 + 3 * WS);   // slots 3-5
    cudaEventRecord(eQKV2W, sPrep);
    cvt16<<<4096, 256, 0, sPrep>>>(enc, e16);
    // KV2 projection — depends only on enc + slots 4-5; co-runs with block 1.
    gemm_qkv<1><<<gKV, 128, G16_SMEM, sPrep>>>(e16, W16 + 4 * WS, nullptr, bk2, bv2,
                                               nullptr, k2, v2, M_ROWS, E_DIM);
    cudaEventRecord(eKV2, sPrep);
    wt_cvt16<<<dim3(32, 32), 256, 0, sPrep>>>(Wo1, W16 + 6 * WS, 1024, 1024);
    cudaEventRecord(eWo1, sPrep);
    wt_cvt16<<<dim3(32, 32), 256, 0, sPrep>>>(Wo2, W16 + 7 * WS, 1024, 1024);
    cudaEventRecord(eWo2, sPrep);
    wt_cvt16<<<dim3(128, 32), 256, 0, sPrep>>>(Wup, W16 + 8 * WS, 1024, 4096);
    cudaEventRecord(eWup, sPrep);
    wt_cvt16<<<dim3(32, 128), 256, 0, sPrep>>>(Wdn, W16 + 12 * WS, 4096, 1024);
    cudaEventRecord(eWdn, sPrep);

    // ---- main chain ----
    ln_kernel<<<M_ROWS / 2, 256>>>(x, ln1g, ln1b, h16);
    cudaStreamWaitEvent(0, eQKV1W, 0);
    gemm_qkv<0><<<gQKV, 128, G16_SMEM>>>(h16, W16, bq1, bk1, bv1,
                                         q16, k16, v16, M_ROWS, E_DIM);
    attn16<true><<<gAttn, 128, ATTN_SMEM>>>(q16, k16, v16, a16);
    cudaStreamWaitEvent(0, eWo1, 0);
    gemm16<2><<<gSq, 128, G16_SMEM>>>(a16, W16 + 6 * WS, bo1, x,
                                      x1, nullptr, M_ROWS, E_DIM, E_DIM);

    ln_kernel<<<M_ROWS / 2, 256>>>(x1, ln2g, ln2b, h16);
    cudaStreamWaitEvent(0, eQKV2W, 0);
    gemm16<0><<<gSq, 128, G16_SMEM>>>(h16, W16 + 3 * WS, bq2, nullptr,
                                      nullptr, q16, M_ROWS, E_DIM, E_DIM);
    cudaStreamWaitEvent(0, eKV2, 0);
    attn16<false><<<gAttn, 128, ATTN_SMEM>>>(q16, k2, v2, a16);
    cudaStreamWaitEvent(0, eWo2, 0);
    gemm16<2><<<gSq, 128, G16_SMEM>>>(a16, W16 + 7 * WS, bo2, x1,
                                      x2, nullptr, M_ROWS, E_DIM, E_DIM);

    ln_kernel<<<M_ROWS / 2, 256>>>(x2, ln3g, ln3b, h16);
    cudaStreamWaitEvent(0, eWup, 0);
    gemm16<1><<<gUp, 128, G16_SMEM>>>(h16, W16 + 8 * WS, bup, nullptr,
                                      nullptr, a16, M_ROWS, F_DIM, E_DIM);
    cudaStreamWaitEvent(0, eWdn, 0);
    gemm16<2><<<gSq, 128, G16_SMEM>>>(a16, W16 + 12 * WS, bdn, x2,
                                      out, nullptr, M_ROWS, E_DIM, F_DIM);
}

// round 17
// speedup vs baseline: 1.0359x; 1.0150x over previous
#include <cuda_runtime.h>
#include <cuda_fp16.h>
#include <math.h>
#include <cstdint>

#define E_DIM 1024
#define H_NUM 16
#define D_DIM 64
#define B_NUM 4
#define S_LEN 1024
#define F_DIM 4096
#define M_ROWS (B_NUM * S_LEN)  // 4096
#define MB1 (1024 * 1024)

// ---------------- scratch (static device globals) ---------------------------
// Weight slots (single fp16, [N][K] transposed): QKV1 0-2, QKV2 3-5, Wo1 6, Wo2 7,
// Wup 8-11, Wdn 12-15.
__device__ __align__(16) half g_W16[16 * MB1];
__device__ __align__(16) half g_h16[4 * MB1];          // LN out
__device__ __align__(16) half g_e16[4 * MB1];          // enc
__device__ __align__(16) half g_q16[4 * MB1];          // Q
__device__ __align__(16) half g_k16[4 * MB1];          // K1
__device__ __align__(16) half g_v16[4 * MB1];          // V1
__device__ __align__(16) half g_k2[4 * MB1];           // K2
__device__ __align__(16) half g_v2[4 * MB1];           // V2
__device__ __align__(16) half g_a16[16 * MB1];         // attn out / GELU out
__device__ __align__(16) float g_x1[4 * MB1], g_x2[4 * MB1];

// ---------------- PTX helpers -----------------------------------------------
__device__ __forceinline__ uint32_t smem_u32(const void* p) {
    uint32_t a;
    asm("{ .reg .u64 t; cvta.to.shared.u64 t, %1; cvt.u32.u64 %0, t; }" : "=r"(a) : "l"(p));
    return a;
}
__device__ __forceinline__ void cpasync16(uint32_t dst, const void* src) {
    asm volatile("cp.async.cg.shared.global [%0], [%1], 16;" :: "r"(dst), "l"(src));
}
__device__ __forceinline__ void cpcommit() { asm volatile("cp.async.commit_group;" ::: "memory"); }
template <int N>
__device__ __forceinline__ void cpwait() { asm volatile("cp.async.wait_group %0;" :: "n"(N) : "memory"); }

__device__ __forceinline__ void ldsm4(uint32_t (&r)[4], uint32_t addr) {
    asm volatile("ldmatrix.sync.aligned.m8n8.x4.shared.b16 {%0,%1,%2,%3}, [%4];"
                 : "=r"(r[0]), "=r"(r[1]), "=r"(r[2]), "=r"(r[3]) : "r"(addr));
}
__device__ __forceinline__ void ldsm4t(uint32_t (&r)[4], uint32_t addr) {
    asm volatile("ldmatrix.sync.aligned.m8n8.x4.trans.shared.b16 {%0,%1,%2,%3}, [%4];"
                 : "=r"(r[0]), "=r"(r[1]), "=r"(r[2]), "=r"(r[3]) : "r"(addr));
}
__device__ __forceinline__ void mma16816h(float (&d)[4], const uint32_t (&a)[4],
                                          const uint32_t (&b)[2]) {
    asm volatile(
        "mma.sync.aligned.m16n8k16.row.col.f32.f16.f16.f32 "
        "{%0,%1,%2,%3}, {%4,%5,%6,%7}, {%8,%9}, {%0,%1,%2,%3};"
        : "+f"(d[0]), "+f"(d[1]), "+f"(d[2]), "+f"(d[3])
        : "r"(a[0]), "r"(a[1]), "r"(a[2]), "r"(a[3]), "r"(b[0]), "r"(b[1]));
}
__device__ __forceinline__ uint32_t swz128(uint32_t o) { return o ^ ((o >> 3) & 0x70); }

__device__ __forceinline__ void packh2(float a, float b, uint32_t& r) {
    half2 p; p.x = __float2half_rn(a); p.y = __float2half_rn(b);
    r = *(uint32_t*)&p;
}

// ---------------- weight prep (vectorized transposes) --------------------------
__global__ void __launch_bounds__(256) wqkv_cvt3(
    const float* __restrict__ w0, const float* __restrict__ w1,
    const float* __restrict__ w2, half* __restrict__ o16) {
    __shared__ float tile[32][33];
    int dt = blockIdx.x;
    int et = blockIdx.y;
    int z  = blockIdx.z;            // s*16 + h, s in 0..2
    int s = z >> 4, h = z & 15;
    const float* src = (s == 0) ? w0 : (s == 1 ? w1 : w2);
    int t = threadIdx.x;
    int e0 = et * 32, d0 = dt * 32;
    {
        int e = t >> 3, d4 = (t & 7) << 2;
        float4 v = *(const float4*)(src + (size_t)h * (E_DIM * D_DIM)
                                    + (size_t)(e0 + e) * D_DIM + d0 + d4);
        tile[e][d4 + 0] = v.x; tile[e][d4 + 1] = v.y;
        tile[e][d4 + 2] = v.z; tile[e][d4 + 3] = v.w;
    }
    __syncthreads();
    {
        int d = t >> 3, e4 = (t & 7) << 2;
        uint32_t lo, hi;
        packh2(tile[e4 + 0][d], tile[e4 + 1][d], lo);
        packh2(tile[e4 + 2][d], tile[e4 + 3][d], hi);
        uint2 pk; pk.x = lo; pk.y = hi;
        size_t oidx = (size_t)s * MB1 + (size_t)(h * 64 + d0 + d) * E_DIM + e0 + e4;
        *(uint2*)(o16 + oidx) = pk;
    }
}
__global__ void __launch_bounds__(256) wt_cvt16(const float* __restrict__ src,
                                                half* __restrict__ o16, int K, int N) {
    __shared__ float tile[32][33];
    int n0 = blockIdx.x * 32, k0 = blockIdx.y * 32;
    int t = threadIdx.x;
    {
        int k = t >> 3, n4 = (t & 7) << 2;
        float4 v = *(const float4*)(src + (size_t)(k0 + k) * N + n0 + n4);
        tile[k][n4 + 0] = v.x; tile[k][n4 + 1] = v.y;
        tile[k][n4 + 2] = v.z; tile[k][n4 + 3] = v.w;
    }
    __syncthreads();
    {
        int n = t >> 3, k4 = (t & 7) << 2;
        uint32_t lo, hi;
        packh2(tile[k4 + 0][n], tile[k4 + 1][n], lo);
        packh2(tile[k4 + 2][n], tile[k4 + 3][n], hi);
        uint2 pk; pk.x = lo; pk.y = hi;
        *(uint2*)(o16 + (size_t)(n0 + n) * K + k0 + k4) = pk;
    }
}
__global__ void cvt16(const float* __restrict__ src, half* __restrict__ dst) {
    int i = blockIdx.x * 256 + threadIdx.x;
    float4 v = ((const float4*)src)[i];
    uint32_t p0, p1;
    packh2(v.x, v.y, p0);
    packh2(v.z, v.w, p1);
    *(uint32_t*)(dst + 4 * (size_t)i) = p0;
    *(uint32_t*)(dst + 4 * (size_t)i + 2) = p1;
}

// ---------------- LayerNorm: f32 -> single fp16, 2 rows per block --------------
__global__ void __launch_bounds__(256) ln_kernel(const float* __restrict__ x,
                                                 const float* __restrict__ g,
                                                 const float* __restrict__ b,
                                                 half* __restrict__ o16) {
    int row0 = blockIdx.x * 2;
    int t = threadIdx.x;
    const float4* xr = (const float4*)(x + (size_t)row0 * E_DIM);
    float4 va = xr[t];
    float4 vb = xr[256 + t];
    float sa = va.x + va.y + va.z + va.w;
    float qa = va.x * va.x + va.y * va.y + va.z * va.z + va.w * va.w;
    float sbv = vb.x + vb.y + vb.z + vb.w;
    float qb = vb.x * vb.x + vb.y * vb.y + vb.z * vb.z + vb.w * vb.w;
    #pragma unroll
    for (int o = 16; o > 0; o >>= 1) {
        sa  += __shfl_xor_sync(0xffffffffu, sa, o);
        qa  += __shfl_xor_sync(0xffffffffu, qa, o);
        sbv += __shfl_xor_sync(0xffffffffu, sbv, o);
        qb  += __shfl_xor_sync(0xffffffffu, qb, o);
    }
    __shared__ float red[4][8];
    int w = t >> 5, lane = t & 31;
    if (lane == 0) { red[0][w] = sa; red[1][w] = qa; red[2][w] = sbv; red[3][w] = qb; }
    __syncthreads();
    sa = 0.0f; qa = 0.0f; sbv = 0.0f; qb = 0.0f;
    #pragma unroll
    for (int i = 0; i < 8; i++) {
        sa += red[0][i]; qa += red[1][i]; sbv += red[2][i]; qb += red[3][i];
    }
    float mua  = sa * (1.0f / E_DIM);
    float inva = rsqrtf(qa * (1.0f / E_DIM) - mua * mua + 1e-5f);
    float mub  = sbv * (1.0f / E_DIM);
    float invb = rsqrtf(qb * (1.0f / E_DIM) - mub * mub + 1e-5f);
    float4 gv = ((const float4*)g)[t];
    float4 bv = ((const float4*)b)[t];
    size_t base = (size_t)row0 * E_DIM + t * 4;
    uint32_t p0, p1;
    packh2((va.x - mua) * inva * gv.x + bv.x, (va.y - mua) * inva * gv.y + bv.y, p0);
    packh2((va.z - mua) * inva * gv.z + bv.z, (va.w - mua) * inva * gv.w + bv.w, p1);
    *(uint32_t*)(o16 + base) = p0;
    *(uint32_t*)(o16 + base + 2) = p1;
    packh2((vb.x - mub) * invb * gv.x + bv.x, (vb.y - mub) * invb * gv.y + bv.y, p0);
    packh2((vb.z - mub) * invb * gv.z + bv.z, (vb.w - mub) * invb * gv.w + bv.w, p1);
    *(uint32_t*)(o16 + base + E_DIM) = p0;
    *(uint32_t*)(o16 + base + E_DIM + 2) = p1;
}

#define G16_STAGE 32768
#define G16_SMEM (2 * G16_STAGE + 256)

// ---------------- fp16 GEMM, 256 threads, 8 warps (4m x 2n), warp tile 32x64 ----
// EPI: 0 bias -> fp16 single, 1 bias+GELU -> fp16, 2 bias+res -> f32
template <int EPI>
__global__ void __launch_bounds__(256, 2) gemm16(
    const half* __restrict__ A, const half* __restrict__ B,
    const float* __restrict__ bias, const float* __restrict__ res,
    float* __restrict__ outF, half* __restrict__ outH,
    int M, int N, int K) {
    extern __shared__ char dyn[];
    uint32_t sb = (smem_u32(dyn) + 127) & ~127u;
    int tid = threadIdx.x, lane = tid & 31, wid = tid >> 5;
    int rBase = blockIdx.y * 128, cBase = blockIdx.x * 128;
    int m0 = (wid >> 1) * 32, n0 = (wid & 1) * 64;

    float acc[2][8][4];
    #pragma unroll
    for (int i = 0; i < 2; i++)
        #pragma unroll
        for (int j = 0; j < 8; j++)
            #pragma unroll
            for (int u = 0; u < 4; u++) acc[i][j][u] = 0.0f;

    const int nc = K >> 6;
    auto loadStage = [&](int s, int c) {
        uint32_t base = sb + s * G16_STAGE;
        int k0 = c << 6;
        #pragma unroll
        for (int i = 0; i < 4; i++) {
            int idx = i * 256 + tid;
            int row = idx >> 3, c16 = idx & 7;
            uint32_t off = swz128(row * 128 + c16 * 16);
            cpasync16(base + off,         A + (size_t)(rBase + row) * K + k0 + c16 * 8);
            cpasync16(base + 16384 + off, B + (size_t)(cBase + row) * K + k0 + c16 * 8);
        }
    };

    int aRow = (lane & 7) + ((lane >> 3) & 1) * 8;
    int aC   = lane >> 4;
    int bRow16 = (lane & 7) + ((lane >> 4) & 1) * 8;
    int bH     = (lane >> 3) & 1;

    loadStage(0, 0); cpcommit();

    for (int c = 0; c < nc; c++) {
        if (c + 1 < nc) { loadStage((c + 1) & 1, c + 1); cpcommit(); cpwait<1>(); }
        else            { cpwait<0>(); }
        __syncthreads();
        uint32_t base = sb + (c & 1) * G16_STAGE;
        #pragma unroll
        for (int kc = 0; kc < 4; kc++) {
            uint32_t bh[8][2];
            #pragma unroll
            for (int jp = 0; jp < 4; jp++) {
                int row = n0 + jp * 16 + bRow16;
                uint32_t t4[4];
                ldsm4(t4, base + 16384 + swz128(row * 128 + kc * 32 + bH * 16));
                bh[2 * jp][0] = t4[0]; bh[2 * jp][1] = t4[1];
                bh[2 * jp + 1][0] = t4[2]; bh[2 * jp + 1][1] = t4[3];
            }
            #pragma unroll
            for (int i = 0; i < 2; i++) {
                uint32_t a4[4];
                int row = m0 + i * 16 + aRow;
                ldsm4(a4, base + swz128(row * 128 + kc * 32 + aC * 16));
                #pragma unroll
                for (int j = 0; j < 8; j++)
                    mma16816h(acc[i][j], a4, bh[j]);
            }
        }
        __syncthreads();
    }

    int lr = lane >> 2, lc = (lane & 3) << 1;
    #pragma unroll
    for (int i = 0; i < 2; i++) {
        #pragma unroll
        for (int half_ = 0; half_ < 2; half_++) {
            size_t row = (size_t)(rBase + m0 + i * 16 + lr + half_ * 8);
            #pragma unroll
            for (int j = 0; j < 8; j++) {
                int col = cBase + n0 + j * 8 + lc;
                float v0 = acc[i][j][half_ * 2 + 0] + bias[col];
                float v1 = acc[i][j][half_ * 2 + 1] + bias[col + 1];
                if (EPI == 0) {
                    uint32_t p;
                    packh2(v0, v1, p);
                    *(uint32_t*)(outH + row * N + col) = p;
                } else if (EPI == 1) {
                    v0 = 0.5f * v0 * (1.0f + erff(v0 * 0.70710678118654752f));
                    v1 = 0.5f * v1 * (1.0f + erff(v1 * 0.70710678118654752f));
                    uint32_t p;
                    packh2(v0, v1, p);
                    *(uint32_t*)(outH + row * N + col) = p;
                } else {
                    float2 rv = *(const float2*)(res + row * N + col);
                    float2 o; o.x = v0 + rv.x; o.y = v1 + rv.y;
                    *(float2*)(outF + row * N + col) = o;
                }
            }
        }
    }
}

// ---------------- fused QKV / KV projection GEMM (256 thr, 8 warps) -------------
// MODE 0 (N=3072): region r -> out[r] with bias[r]  (Q, K, V — all single fp16)
// MODE 1 (N=2048): region 0 -> o1/b1 (K), region 1 -> o2/b2 (V)
template <int MODE>
__global__ void __launch_bounds__(256, 2) gemm_qkv(
    const half* __restrict__ A, const half* __restrict__ B,
    const float* __restrict__ b0, const float* __restrict__ b1,
    const float* __restrict__ b2,
    half* __restrict__ o0, half* __restrict__ o1, half* __restrict__ o2,
    int M, int K) {
    extern __shared__ char dyn[];
    uint32_t sb = (smem_u32(dyn) + 127) & ~127u;
    int tid = threadIdx.x, lane = tid & 31, wid = tid >> 5;
    int rBase = blockIdx.y * 128, cBase = blockIdx.x * 128;
    int m0 = (wid >> 1) * 32, n0 = (wid & 1) * 64;

    float acc[2][8][4];
    #pragma unroll
    for (int i = 0; i < 2; i++)
        #pragma unroll
        for (int j = 0; j < 8; j++)
            #pragma unroll
            for (int u = 0; u < 4; u++) acc[i][j][u] = 0.0f;

    const int nc = K >> 6;
    auto loadStage = [&](int s, int c) {
        uint32_t base = sb + s * G16_STAGE;
        int k0 = c << 6;
        #pragma unroll
        for (int i = 0; i < 4; i++) {
            int idx = i * 256 + tid;
            int row = idx >> 3, c16 = idx & 7;
            uint32_t off = swz128(row * 128 + c16 * 16);
            cpasync16(base + off,         A + (size_t)(rBase + row) * K + k0 + c16 * 8);
            cpasync16(base + 16384 + off, B + (size_t)(cBase + row) * K + k0 + c16 * 8);
        }
    };

    int aRow = (lane & 7) + ((lane >> 3) & 1) * 8;
    int aC   = lane >> 4;
    int bRow16 = (lane & 7) + ((lane >> 4) & 1) * 8;
    int bH     = (lane >> 3) & 1;

    loadStage(0, 0); cpcommit();

    for (int c = 0; c < nc; c++) {
        if (c + 1 < nc) { loadStage((c + 1) & 1, c + 1); cpcommit(); cpwait<1>(); }
        else            { cpwait<0>(); }
        __syncthreads();
        uint32_t base = sb + (c & 1) * G16_STAGE;
        #pragma unroll
        for (int kc = 0; kc < 4; kc++) {
            uint32_t bh[8][2];
            #pragma unroll
            for (int jp = 0; jp < 4; jp++) {
                int row = n0 + jp * 16 + bRow16;
                uint32_t t4[4];
                ldsm4(t4, base + 16384 + swz128(row * 128 + kc * 32 + bH * 16));
                bh[2 * jp][0] = t4[0]; bh[2 * jp][1] = t4[1];
                bh[2 * jp + 1][0] = t4[2]; bh[2 * jp + 1][1] = t4[3];
            }
            #pragma unroll
            for (int i = 0; i < 2; i++) {
                uint32_t a4[4];
                int row = m0 + i * 16 + aRow;
                ldsm4(a4, base + swz128(row * 128 + kc * 32 + aC * 16));
                #pragma unroll
                for (int j = 0; j < 8; j++)
                    mma16816h(acc[i][j], a4, bh[j]);
            }
        }
        __syncthreads();
    }

    int region = cBase >> 10;
    int cLoc = (cBase & 1023) + n0;
    const float* bias;
    half* outS;
    if (MODE == 0) {
        bias = (region == 0) ? b0 : (region == 1 ? b1 : b2);
        outS = (region == 0) ? o0 : (region == 1 ? o1 : o2);
    } else {
        bias = (region == 0) ? b1 : b2;
        outS = (region == 0) ? o1 : o2;
    }

    int lr = lane >> 2, lc = (lane & 3) << 1;
    #pragma unroll
    for (int i = 0; i < 2; i++) {
        #pragma unroll
        for (int half_ = 0; half_ < 2; half_++) {
            size_t row = (size_t)(rBase + m0 + i * 16 + lr + half_ * 8);
            #pragma unroll
            for (int j = 0; j < 8; j++) {
                int col = cLoc + j * 8 + lc;
                float v0 = acc[i][j][half_ * 2 + 0] + bias[col];
                float v1 = acc[i][j][half_ * 2 + 1] + bias[col + 1];
                uint32_t p;
                packh2(v0, v1, p);
                *(uint32_t*)(outS + row * E_DIM + col) = p;
            }
        }
    }
}

// ---------------- flash attention (D=64): all-single fp16, 2-stage -------------
// grid (S/64, H, B), 128 threads, 3 CTAs/SM. (unchanged — tuned)
#define ATTN_SMEM (8192 + 2 * 16384 + 1024)
template <bool CAUSAL>
__global__ void __launch_bounds__(128, 3) attn16(
    const half* __restrict__ Q, const half* __restrict__ K,
    const half* __restrict__ V, half* __restrict__ O) {
    extern __shared__ char dyn[];
    uint32_t sb = (smem_u32(dyn) + 1023) & ~1023u;
    int tid = threadIdx.x, lane = tid & 31, w = tid >> 5;
    int b = blockIdx.z, hh = blockIdx.y;
    int qt = CAUSAL ? ((int)gridDim.x - 1 - (int)blockIdx.x) : (int)blockIdx.x;
    size_t headOff = (size_t)hh * D_DIM;
    size_t tokBase = (size_t)b * S_LEN;

    int aRow = (lane & 7) + ((lane >> 3) & 1) * 8;
    int aC = lane >> 4;

    {
        #pragma unroll
        for (int i = 0; i < 4; i++) {
            int idx = i * 128 + tid;
            int r = idx >> 3, c = idx & 7;
            uint32_t off = swz128(r * 128 + c * 16);
            cpasync16(sb + off, Q + (tokBase + qt * 64 + r) * E_DIM + headOff + c * 8);
        }
    }
    auto loadKV = [&](int s, int kt) {
        uint32_t base = sb + 8192 + s * 16384;
        #pragma unroll
        for (int i = 0; i < 4; i++) {
            int idx = i * 128 + tid;
            int r = idx >> 3, c = idx & 7;
            uint32_t off = swz128(r * 128 + c * 16);
            size_t src = (tokBase + kt * 64 + r) * E_DIM + headOff + c * 8;
            cpasync16(base + off,        K + src);
            cpasync16(base + 8192 + off, V + src);
        }
    };
    loadKV(0, 0);
    cpcommit();

    uint32_t qf[4][4];
    float oacc[8][4];
    float mrow[2] = {-1e30f, -1e30f}, lrow[2] = {0.0f, 0.0f};
    #pragma unroll
    for (int j = 0; j < 8; j++)
        #pragma unroll
        for (int u = 0; u < 4; u++) oacc[j][u] = 0.0f;

    const int ntiles = CAUSAL ? (qt + 1) : (S_LEN / 64);
    for (int kt = 0; kt < ntiles; kt++) {
        if (kt + 1 < ntiles) { loadKV((kt + 1) & 1, kt + 1); cpcommit(); cpwait<1>(); }
        else                 { cpwait<0>(); }
        __syncthreads();
        if (kt == 0) {
            #pragma unroll
            for (int s = 0; s < 4; s++)
                ldsm4(qf[s], sb + swz128((w * 16 + aRow) * 128 + s * 32 + aC * 16));
        }
        uint32_t kb = sb + 8192 + (kt & 1) * 16384;
        uint32_t vb = kb + 8192;

        float sacc[8][4];
        #pragma unroll
        for (int j = 0; j < 8; j++)
            #pragma unroll
            for (int u = 0; u < 4; u++) sacc[j][u] = 0.0f;
        #pragma unroll
        for (int s = 0; s < 4; s++) {
            #pragma unroll
            for (int jp = 0; jp < 4; jp++) {
                uint32_t k4[4];
                ldsm4(k4, kb + swz128((jp * 16 + aRow) * 128 + s * 32 + aC * 16));
                uint32_t b0[2] = {k4[0], k4[2]}, b1[2] = {k4[1], k4[3]};
                mma16816h(sacc[2 * jp],     qf[s], b0);
                mma16816h(sacc[2 * jp + 1], qf[s], b1);
            }
        }

        if (CAUSAL && kt == qt) {
            int ql0 = w * 16 + (lane >> 2);
            #pragma unroll
            for (int j = 0; j < 8; j++)
                #pragma unroll
                for (int u = 0; u < 4; u++) {
                    int kcol = j * 8 + ((lane & 3) << 1) + (u & 1);
                    int qrow = ql0 + (u >> 1) * 8;
                    if (kcol > qrow) sacc[j][u] = -1e30f;
                }
        }

        #pragma unroll
        for (int h2 = 0; h2 < 2; h2++) {
            float mt = -1e30f;
            #pragma unroll
            for (int j = 0; j < 8; j++)
                mt = fmaxf(mt, fmaxf(sacc[j][2 * h2], sacc[j][2 * h2 + 1]));
            mt = fmaxf(mt, __shfl_xor_sync(0xffffffffu, mt, 1));
            mt = fmaxf(mt, __shfl_xor_sync(0xffffffffu, mt, 2));
            float mn = fmaxf(mrow[h2], mt);
            float sc = __expf(mrow[h2] - mn);
            mrow[h2] = mn;
            float ts = 0.0f;
            #pragma unroll
            for (int j = 0; j < 8; j++) {
                sacc[j][2 * h2]     = __expf(sacc[j][2 * h2] - mn);
                sacc[j][2 * h2 + 1] = __expf(sacc[j][2 * h2 + 1] - mn);
                ts += sacc[j][2 * h2] + sacc[j][2 * h2 + 1];
            }
            ts += __shfl_xor_sync(0xffffffffu, ts, 1);
            ts += __shfl_xor_sync(0xffffffffu, ts, 2);
            lrow[h2] = lrow[h2] * sc + ts;
            #pragma unroll
            for (int j = 0; j < 8; j++) {
                oacc[j][2 * h2]     *= sc;
                oacc[j][2 * h2 + 1] *= sc;
            }
        }

        #pragma unroll
        for (int s = 0; s < 4; s++) {
            uint32_t pf[4];
            packh2(sacc[2 * s][0],     sacc[2 * s][1],     pf[0]);
            packh2(sacc[2 * s][2],     sacc[2 * s][3],     pf[1]);
            packh2(sacc[2 * s + 1][0], sacc[2 * s + 1][1], pf[2]);
            packh2(sacc[2 * s + 1][2], sacc[2 * s + 1][3], pf[3]);
            #pragma unroll
            for (int jp = 0; jp < 4; jp++) {
                uint32_t v4[4];
                ldsm4t(v4, vb + swz128((s * 16 + aRow) * 128 + jp * 32 + aC * 16));
                uint32_t b0[2] = {v4[0], v4[1]}, b1[2] = {v4[2], v4[3]};
                mma16816h(oacc[2 * jp],     pf, b0);
                mma16816h(oacc[2 * jp + 1], pf, b1);
            }
        }
        __syncthreads();
    }

    #pragma unroll
    for (int h2 = 0; h2 < 2; h2++) {
        float inv = 1.0f / lrow[h2];
        int trow = qt * 64 + w * 16 + (lane >> 2) + h2 * 8;
        size_t rp = (tokBase + trow) * E_DIM + headOff;
        #pragma unroll
        for (int j = 0; j < 8; j++) {
            uint32_t p;
            packh2(oacc[j][2 * h2] * inv, oacc[j][2 * h2 + 1] * inv, p);
            int col = j * 8 + ((lane & 3) << 1);
            *(uint32_t*)(O + rp + col) = p;
        }
    }
}

// ---------------- launch ------------------------------------------------------
extern "C" void kernel_launch(void* const* d_in, const int* in_sizes, int n_in,
                              void* d_out, int out_size) {
    const float* x    = (const float*)d_in[0];
    const float* enc  = (const float*)d_in[1];
    const float* ln1g = (const float*)d_in[2];
    const float* ln1b = (const float*)d_in[3];
    const float* ln2g = (const float*)d_in[4];
    const float* ln2b = (const float*)d_in[5];
    const float* ln3g = (const float*)d_in[6];
    const float* ln3b = (const float*)d_in[7];
    const float* Wq1  = (const float*)d_in[8];
    const float* bq1  = (const float*)d_in[9];
    const float* Wk1  = (const float*)d_in[10];
    const float* bk1  = (const float*)d_in[11];
    const float* Wv1  = (const float*)d_in[12];
    const float* bv1  = (const float*)d_in[13];
    const float* Wo1  = (const float*)d_in[14];
    const float* bo1  = (const float*)d_in[15];
    const float* Wq2  = (const float*)d_in[16];
    const float* bq2  = (const float*)d_in[17];
    const float* Wk2  = (const float*)d_in[18];
    const float* bk2  = (const float*)d_in[19];
    const float* Wv2  = (const float*)d_in[20];
    const float* bv2  = (const float*)d_in[21];
    const float* Wo2  = (const float*)d_in[22];
    const float* bo2  = (const float*)d_in[23];
    const float* Wup  = (const float*)d_in[24];
    const float* bup  = (const float*)d_in[25];
    const float* Wdn  = (const float*)d_in[26];
    const float* bdn  = (const float*)d_in[27];
    float* out = (float*)d_out;

    half *W16, *h16, *e16, *q16, *k16, *v16, *k2, *v2, *a16;
    float *x1, *x2;
    cudaGetSymbolAddress((void**)&W16, g_W16);
    cudaGetSymbolAddress((void**)&h16, g_h16);
    cudaGetSymbolAddress((void**)&e16, g_e16);
    cudaGetSymbolAddress((void**)&q16, g_q16);
    cudaGetSymbolAddress((void**)&k16, g_k16);
    cudaGetSymbolAddress((void**)&v16, g_v16);
    cudaGetSymbolAddress((void**)&k2,  g_k2);
    cudaGetSymbolAddress((void**)&v2,  g_v2);
    cudaGetSymbolAddress((void**)&a16, g_a16);
    cudaGetSymbolAddress((void**)&x1,  g_x1);
    cudaGetSymbolAddress((void**)&x2,  g_x2);

    cudaFuncSetAttribute(gemm16<0>, cudaFuncAttributeMaxDynamicSharedMemorySize, G16_SMEM);
    cudaFuncSetAttribute(gemm16<1>, cudaFuncAttributeMaxDynamicSharedMemorySize, G16_SMEM);
    cudaFuncSetAttribute(gemm16<2>, cudaFuncAttributeMaxDynamicSharedMemorySize, G16_SMEM);
    cudaFuncSetAttribute(gemm_qkv<0>, cudaFuncAttributeMaxDynamicSharedMemorySize, G16_SMEM);
    cudaFuncSetAttribute(gemm_qkv<1>, cudaFuncAttributeMaxDynamicSharedMemorySize, G16_SMEM);
    cudaFuncSetAttribute(attn16<true>,  cudaFuncAttributeMaxDynamicSharedMemorySize, ATTN_SMEM);
    cudaFuncSetAttribute(attn16<false>, cudaFuncAttributeMaxDynamicSharedMemorySize, ATTN_SMEM);

    static cudaStream_t sPrep = nullptr;
    static cudaEvent_t eFork, eQKV1W, eQKV2W, eKV2, eWo1, eWo2, eWup, eWdn;
    if (sPrep == nullptr) {
        cudaStreamCreateWithFlags(&sPrep, cudaStreamNonBlocking);
        cudaEventCreateWithFlags(&eFork,  cudaEventDisableTiming);
        cudaEventCreateWithFlags(&eQKV1W, cudaEventDisableTiming);
        cudaEventCreateWithFlags(&eQKV2W, cudaEventDisableTiming);
        cudaEventCreateWithFlags(&eKV2,   cudaEventDisableTiming);
        cudaEventCreateWithFlags(&eWo1,   cudaEventDisableTiming);
        cudaEventCreateWithFlags(&eWo2,   cudaEventDisableTiming);
        cudaEventCreateWithFlags(&eWup,   cudaEventDisableTiming);
        cudaEventCreateWithFlags(&eWdn,   cudaEventDisableTiming);
    }

    const int WS = E_DIM * E_DIM;
    dim3 gSq(8, 32);
    dim3 gUp(32, 32);
    dim3 gQKV(24, 32);
    dim3 gKV(16, 32);
    dim3 gAttn(S_LEN / 64, H_NUM, B_NUM);

    // ---- fork prep stream (KV2 launched as early as deps allow) ----
    cudaEventRecord(eFork, 0);
    cudaStreamWaitEvent(sPrep, eFork, 0);
    wqkv_cvt3<<<dim3(2, 32, 48), 256, 0, sPrep>>>(Wq1, Wk1, Wv1, W16);            // slots 0-2
    cudaEventRecord(eQKV1W, sPrep);
    wqkv_cvt3<<<dim3(2, 32, 48), 256, 0, sPrep>>>(Wq2, Wk2, Wv2, W16 + 3 * WS);   // slots 3-5
    cudaEventRecord(eQKV2W, sPrep);
    cvt16<<<4096, 256, 0, sPrep>>>(enc, e16);
    gemm_qkv<1><<<gKV, 256, G16_SMEM, sPrep>>>(e16, W16 + 4 * WS, nullptr, bk2, bv2,
                                               nullptr, k2, v2, M_ROWS, E_DIM);
    cudaEventRecord(eKV2, sPrep);
    wt_cvt16<<<dim3(32, 32), 256, 0, sPrep>>>(Wo1, W16 + 6 * WS, 1024, 1024);
    cudaEventRecord(eWo1, sPrep);
    wt_cvt16<<<dim3(32, 32), 256, 0, sPrep>>>(Wo2, W16 + 7 * WS, 1024, 1024);
    cudaEventRecord(eWo2, sPrep);
    wt_cvt16<<<dim3(128, 32), 256, 0, sPrep>>>(Wup, W16 + 8 * WS, 1024, 4096);
    cudaEventRecord(eWup, sPrep);
    wt_cvt16<<<dim3(32, 128), 256, 0, sPrep>>>(Wdn, W16 + 12 * WS, 4096, 1024);
    cudaEventRecord(eWdn, sPrep);

    // ---- main chain ----
    ln_kernel<<<M_ROWS / 2, 256>>>(x, ln1g, ln1b, h16);
    cudaStreamWaitEvent(0, eQKV1W, 0);
    gemm_qkv<0><<<gQKV, 256, G16_SMEM>>>(h16, W16, bq1, bk1, bv1,
                                         q16, k16, v16, M_ROWS, E_DIM);
    attn16<true><<<gAttn, 128, ATTN_SMEM>>>(q16, k16, v16, a16);
    cudaStreamWaitEvent(0, eWo1, 0);
    gemm16<2><<<gSq, 256, G16_SMEM>>>(a16, W16 + 6 * WS, bo1, x,
                                      x1, nullptr, M_ROWS, E_DIM, E_DIM);

    ln_kernel<<<M_ROWS / 2, 256>>>(x1, ln2g, ln2b, h16);
    cudaStreamWaitEvent(0, eQKV2W, 0);
    gemm16<0><<<gSq, 256, G16_SMEM>>>(h16, W16 + 3 * WS, bq2, nullptr,
                                      nullptr, q16, M_ROWS, E_DIM, E_DIM);
    cudaStreamWaitEvent(0, eKV2, 0);
    attn16<false><<<gAttn, 128, ATTN_SMEM>>>(q16, k2, v2, a16);
    cudaStreamWaitEvent(0, eWo2, 0);
    gemm16<2><<<gSq, 256, G16_SMEM>>>(a16, W16 + 7 * WS, bo2, x1,
                                      x2, nullptr, M_ROWS, E_DIM, E_DIM);

    ln_kernel<<<M_ROWS / 2, 256>>>(x2, ln3g, ln3b, h16);
    cudaStreamWaitEvent(0, eWup, 0);
    gemm16<1><<<gUp, 256, G16_SMEM>>>(h16, W16 + 8 * WS, bup, nullptr,
                                      nullptr, a16, M_ROWS, F_DIM, E_DIM);
    cudaStreamWaitEvent(0, eWdn, 0);
    gemm16<2><<<gSq, 256, G16_SMEM>>>(a16, W16 + 12 * WS, bdn, x2,
                                      out, nullptr, M_ROWS, E_DIM, F_DIM);
}